// round 7
// baseline (speedup 1.0000x reference)
#include <cuda_runtime.h>
#include <cuda_bf16.h>
#include <cstdint>

#define TFR 4096
#define DM 128
#define LQ 64
#define NG 16
#define FD 2048
#define GFD 512
#define NTOK (TFR * NG)
#define LNE 1e-5f

// ---------------- device-global scratch ------------------------------------
__device__ float g_lnvis[TFR * DM];
__device__ float g_t0ln[NG * DM];
__device__ float g_Q0[NG * DM];
__device__ float g_Kf[NG * DM];
__device__ float g_Vf[NG * DM];
__device__ float g_K[2][TFR * DM];
__device__ float g_V[2][TFR * DM];
__device__ float g_t[NTOK * DM];
__device__ float g_Qp[NTOK * DM];

// transposed ([n][k]) weights, tf32 bit patterns
__device__ uint32_t g_W1t[2][FD * DM];   // [2048][128]
__device__ uint32_t g_W2t[2][DM * FD];   // [128][2048]
__device__ uint32_t g_Wqt[2][DM * DM];
__device__ uint32_t g_Wkt[2][DM * DM];
__device__ uint32_t g_Wvt[2][DM * DM];
__device__ uint32_t g_Wqft[DM * DM];
__device__ uint32_t g_Wvist[DM * FD];    // [128][2048]

__device__ __forceinline__ float warp_sum(float v) {
#pragma unroll
    for (int o = 16; o > 0; o >>= 1) v += __shfl_xor_sync(0xffffffffu, v, o);
    return v;
}
__device__ __forceinline__ uint32_t cvta_s(const void* p) {
    return (uint32_t)__cvta_generic_to_shared(p);
}
__device__ __forceinline__ uint32_t f2tf(float v) {
    uint32_t r;
    asm("cvt.rna.tf32.f32 %0, %1;" : "=r"(r) : "f"(v));
    return r;
}
__device__ __forceinline__ void mma_tf32(float c[4], const uint32_t a[4],
                                         uint32_t b0, uint32_t b1) {
    asm volatile(
        "mma.sync.aligned.m16n8k8.row.col.f32.tf32.tf32.f32 "
        "{%0,%1,%2,%3},{%4,%5,%6,%7},{%8,%9},{%0,%1,%2,%3};"
        : "+f"(c[0]), "+f"(c[1]), "+f"(c[2]), "+f"(c[3])
        : "r"(a[0]), "r"(a[1]), "r"(a[2]), "r"(a[3]), "r"(b0), "r"(b1));
}
// A fragment m16k8 from [m][k] smem (tf32 bits)
__device__ __forceinline__ void ldA(uint32_t a[4], const uint32_t* s, int m0,
                                    int k0, int stride, int lane) {
    int r = m0 + (lane >> 2), c = k0 + (lane & 3);
    a[0] = s[r * stride + c];
    a[1] = s[(r + 8) * stride + c];
    a[2] = s[r * stride + c + 4];
    a[3] = s[(r + 8) * stride + c + 4];
}
// B fragment k8n8 from [n][k] smem
__device__ __forceinline__ void ldB(uint32_t b[2], const uint32_t* s, int n0,
                                    int k0, int stride, int lane) {
    int n = n0 + (lane >> 2), c = k0 + (lane & 3);
    b[0] = s[n * stride + c];
    b[1] = s[n * stride + c + 4];
}
#define CP16(dst, src) \
    asm volatile("cp.async.cg.shared.global [%0], [%1], 16;" :: "r"(dst), "l"(src))
#define CP_COMMIT() asm volatile("cp.async.commit_group;" ::: "memory")
#define CP_WAIT1() asm volatile("cp.async.wait_group 1;" ::: "memory")

// ---------------- fused weight conversion (one launch) ---------------------
// seg: 0,1 W1 | 2,3 W2 | 4,5 Wq | 6,7 Wk | 8,9 Wv | 10 Wqf | 11 Wvis
__global__ void convert_kernel(const float* W1, const float* W2, const float* Wq,
                               const float* Wk, const float* Wv, const float* Wqf,
                               const float* Wvis) {
    int seg = blockIdx.y;
    const float* src;
    uint32_t* dst;
    int K, N;
    switch (seg) {
        case 0:  src = W1;                 dst = g_W1t[0]; K = DM; N = FD; break;
        case 1:  src = W1 + (size_t)DM*FD; dst = g_W1t[1]; K = DM; N = FD; break;
        case 2:  src = W2;                 dst = g_W2t[0]; K = FD; N = DM; break;
        case 3:  src = W2 + (size_t)FD*DM; dst = g_W2t[1]; K = FD; N = DM; break;
        case 4:  src = Wq;                 dst = g_Wqt[0]; K = DM; N = DM; break;
        case 5:  src = Wq + DM*DM;         dst = g_Wqt[1]; K = DM; N = DM; break;
        case 6:  src = Wk;                 dst = g_Wkt[0]; K = DM; N = DM; break;
        case 7:  src = Wk + DM*DM;         dst = g_Wkt[1]; K = DM; N = DM; break;
        case 8:  src = Wv;                 dst = g_Wvt[0]; K = DM; N = DM; break;
        case 9:  src = Wv + DM*DM;         dst = g_Wvt[1]; K = DM; N = DM; break;
        case 10: src = Wqf;                dst = g_Wqft;   K = DM; N = DM; break;
        default: src = Wvis;               dst = g_Wvist;  K = FD; N = DM; break;
    }
    int idx = blockIdx.x * 256 + threadIdx.x;
    if (idx >= K * N) return;
    int k = idx / N, n = idx - k * N;
    dst[(size_t)n * K + k] = f2tf(src[idx]);
}

// ---------------- generic 64-row GEMM, K=128, tf32 single pass --------------
__device__ __forceinline__ void gemm128_core(const float* A, float* C,
                                             const uint32_t* Bt, int a_ln,
                                             uint32_t* smu) {
    uint32_t* sA = smu;              // [64][132]
    uint32_t* sB = smu + 64 * 132;   // [128][132]
    int tid = threadIdx.x, lane = tid & 31, warp = tid >> 5;
    size_t row0 = (size_t)blockIdx.x * 64;

#pragma unroll
    for (int i = 0; i < 8; i++) {
        int r = warp * 8 + i;
        float4 v = *(const float4*)&A[(row0 + r) * DM + lane * 4];
        if (a_ln) {
            float s = v.x + v.y + v.z + v.w;
            float q = v.x * v.x + v.y * v.y + v.z * v.z + v.w * v.w;
            s = warp_sum(s); q = warp_sum(q);
            float m = s * (1.f / DM);
            float rs = rsqrtf(q * (1.f / DM) - m * m + LNE);
            v.x = (v.x - m) * rs; v.y = (v.y - m) * rs;
            v.z = (v.z - m) * rs; v.w = (v.w - m) * rs;
        }
        uint4 t;
        t.x = f2tf(v.x); t.y = f2tf(v.y); t.z = f2tf(v.z); t.w = f2tf(v.w);
        *(uint4*)&sA[r * 132 + lane * 4] = t;
    }
#pragma unroll
    for (int u = 0; u < 16; u++) {
        int e = u * 256 + tid;
        int n = e >> 5, kk = (e & 31) * 4;
        *(uint4*)&sB[n * 132 + kk] = *(const uint4*)&Bt[n * DM + kk];
    }
    __syncthreads();

    int m0 = (warp >> 1) * 16, n0 = (warp & 1) * 64;
    float acc[8][4];
#pragma unroll
    for (int t = 0; t < 8; t++)
#pragma unroll
        for (int j = 0; j < 4; j++) acc[t][j] = 0.f;

#pragma unroll
    for (int ks = 0; ks < 16; ks++) {
        int k0 = ks * 8;
        uint32_t a[4];
        ldA(a, sA, m0, k0, 132, lane);
#pragma unroll
        for (int nt = 0; nt < 8; nt++) {
            uint32_t b[2];
            ldB(b, sB, n0 + nt * 8, k0, 132, lane);
            mma_tf32(acc[nt], a, b[0], b[1]);
        }
    }
    int r = m0 + (lane >> 2), cb = (lane & 3) * 2;
#pragma unroll
    for (int t = 0; t < 8; t++) {
        int col = n0 + t * 8 + cb;
        *(float2*)&C[(row0 + r) * DM + col] = make_float2(acc[t][0], acc[t][1]);
        *(float2*)&C[(row0 + r + 8) * DM + col] = make_float2(acc[t][2], acc[t][3]);
    }
}

__global__ void __launch_bounds__(256) kv_kernel() {
    extern __shared__ uint32_t smg[];
    int s = blockIdx.y;
    const uint32_t* Bt = (s == 0) ? g_Wkt[0] : (s == 1) ? g_Wvt[0]
                       : (s == 2) ? g_Wkt[1] : g_Wvt[1];
    float* C = (s == 0) ? g_K[0] : (s == 1) ? g_V[0] : (s == 2) ? g_K[1] : g_V[1];
    gemm128_core(g_lnvis, C, Bt, 0, smg);
}
__global__ void __launch_bounds__(256) qproj_kernel(int mode) {
    extern __shared__ uint32_t smg[];
    if (mode == 0)
        gemm128_core(g_t, g_Qp, g_Wqt[1], 1, smg);
    else
        gemm128_core(g_t, g_Qp, g_Wqft, 0, smg);
}

// ---------------- visual: lnvis = LN(LF @ Wvis), tf32, K=2048 ---------------
__global__ void __launch_bounds__(256) visual_mma(const float* __restrict__ LF) {
    extern __shared__ uint32_t smv[];
    uint32_t* sA = smv;              // [64][68]
    uint32_t* sB = smv + 64 * 68;    // [128][68]
    float* sY = (float*)smv;         // [64][132] alias (used after MMA loop)
    int tid = threadIdx.x, lane = tid & 31, warp = tid >> 5;
    size_t row0 = (size_t)blockIdx.x * 64;
    int m0 = (warp >> 1) * 16, n0 = (warp & 1) * 64;
    float acc[8][4];
#pragma unroll
    for (int t = 0; t < 8; t++)
#pragma unroll
        for (int j = 0; j < 4; j++) acc[t][j] = 0.f;

    for (int kc = 0; kc < FD; kc += 64) {
#pragma unroll
        for (int u = 0; u < 4; u++) {
            int e = u * 256 + tid;
            int r = e >> 4, c4 = (e & 15) * 4;
            float4 v = *(const float4*)&LF[(row0 + r) * FD + kc + c4];
            uint4 t;
            t.x = f2tf(v.x); t.y = f2tf(v.y); t.z = f2tf(v.z); t.w = f2tf(v.w);
            *(uint4*)&sA[r * 68 + c4] = t;
        }
        // B chunk: 128 rows x 64 u32 = 2048 uint4 (FIXED indexing)
#pragma unroll
        for (int u = 0; u < 8; u++) {
            int e = u * 256 + tid;
            int n = e >> 4, kk = (e & 15) * 4;
            *(uint4*)&sB[n * 68 + kk] = *(const uint4*)&g_Wvist[(size_t)n * FD + kc + kk];
        }
        __syncthreads();
#pragma unroll
        for (int ks = 0; ks < 8; ks++) {
            int k0 = ks * 8;
            uint32_t a[4];
            ldA(a, sA, m0, k0, 68, lane);
#pragma unroll
            for (int nt = 0; nt < 8; nt++) {
                uint32_t b[2];
                ldB(b, sB, n0 + nt * 8, k0, 68, lane);
                mma_tf32(acc[nt], a, b[0], b[1]);
            }
        }
        __syncthreads();
    }
    int r = m0 + (lane >> 2), cb = (lane & 3) * 2;
#pragma unroll
    for (int t = 0; t < 8; t++) {
        int col = n0 + t * 8 + cb;
        sY[r * 132 + col] = acc[t][0];
        sY[r * 132 + col + 1] = acc[t][1];
        sY[(r + 8) * 132 + col] = acc[t][2];
        sY[(r + 8) * 132 + col + 1] = acc[t][3];
    }
    __syncthreads();
#pragma unroll
    for (int i = 0; i < 8; i++) {
        int rr = warp * 8 + i;
        float4 v = *(const float4*)&sY[rr * 132 + lane * 4];
        float s = v.x + v.y + v.z + v.w;
        float q = v.x * v.x + v.y * v.y + v.z * v.z + v.w * v.w;
        s = warp_sum(s); q = warp_sum(q);
        float m = s * (1.f / DM);
        float rs = rsqrtf(q * (1.f / DM) - m * m + LNE);
        float4 o = {(v.x - m) * rs, (v.y - m) * rs, (v.z - m) * rs, (v.w - m) * rs};
        *(float4*)&g_lnvis[(row0 + rr) * DM + lane * 4] = o;
    }
}

// ---------------- FFN: tf32 single-pass, cp.async double-buffered -----------
// smem (uint32 units): sX[128][132]=16896 | W1 2x[32][132]=8448 |
//                      W2 2x[128][36]=9216 | H[128][36]=4608  -> 39168 u32
#define FFN_SMEM (39168 * 4)
#define NCH 64

__global__ void __launch_bounds__(256) ffn_tf32(int l) {
    extern __shared__ uint32_t smf[];
    uint32_t* sX = smf;
    uint32_t* sW1b = smf + 16896;     // stride 4224 per buf
    uint32_t* sW2b = smf + 25344;     // stride 4608 per buf
    uint32_t* sH = smf + 34560;
    const uint32_t* W1 = g_W1t[l];
    const uint32_t* W2 = g_W2t[l];
    int tid = threadIdx.x, lane = tid & 31, warp = tid >> 5;
    size_t row0 = (size_t)blockIdx.x * 128;
    uint32_t sb = cvta_s(smf);

    // prologue: LN + tf32 X
#pragma unroll
    for (int i = 0; i < 16; i++) {
        int r = warp * 16 + i;
        float4 v = *(const float4*)&g_t[(row0 + r) * DM + lane * 4];
        float s = v.x + v.y + v.z + v.w;
        float q = v.x * v.x + v.y * v.y + v.z * v.z + v.w * v.w;
        s = warp_sum(s); q = warp_sum(q);
        float m = s * (1.f / DM);
        float rs = rsqrtf(q * (1.f / DM) - m * m + LNE);
        uint4 t;
        t.x = f2tf((v.x - m) * rs); t.y = f2tf((v.y - m) * rs);
        t.z = f2tf((v.z - m) * rs); t.w = f2tf((v.w - m) * rs);
        *(uint4*)&sX[r * 132 + lane * 4] = t;
    }
    // issue chunk 0 into buf 0
    {
        uint32_t w1d = sb + 16896 * 4, w2d = sb + 25344 * 4;
#pragma unroll
        for (int u = 0; u < 4; u++) {
            int e = u * 256 + tid;
            int n = e >> 5, kk = (e & 31) * 4;
            CP16(w1d + (n * 132 + kk) * 4, W1 + (size_t)n * DM + kk);
        }
#pragma unroll
        for (int u = 0; u < 4; u++) {
            int e = u * 256 + tid;
            int n = e >> 3, kk = (e & 7) * 4;
            CP16(w2d + (n * 36 + kk) * 4, W2 + (size_t)n * FD + kk);
        }
        CP_COMMIT();
    }

    float acc2[16][4];
#pragma unroll
    for (int t = 0; t < 16; t++)
#pragma unroll
        for (int j = 0; j < 4; j++) acc2[t][j] = 0.f;

    int lr = lane >> 2, lc = 2 * (lane & 3);
    for (int i = 0; i < NCH; i++) {
        int buf = i & 1, nb = buf ^ 1;
        __syncthreads();  // all warps done reading buffer nb (iter i-1)
        if (i + 1 < NCH) {
            uint32_t w1d = sb + (16896 + nb * 4224) * 4;
            uint32_t w2d = sb + (25344 + nb * 4608) * 4;
            const uint32_t* W1s = W1 + (size_t)(i + 1) * 32 * DM;
#pragma unroll
            for (int u = 0; u < 4; u++) {
                int e = u * 256 + tid;
                int n = e >> 5, kk = (e & 31) * 4;
                CP16(w1d + (n * 132 + kk) * 4, W1s + (size_t)n * DM + kk);
            }
#pragma unroll
            for (int u = 0; u < 4; u++) {
                int e = u * 256 + tid;
                int n = e >> 3, kk = (e & 7) * 4;
                CP16(w2d + (n * 36 + kk) * 4, W2 + (size_t)n * FD + (i + 1) * 32 + kk);
            }
        }
        CP_COMMIT();
        CP_WAIT1();        // chunk i arrived (own thread's copies)
        __syncthreads();   // everyone's copies visible
        const uint32_t* w1 = sW1b + buf * 4224;
        const uint32_t* w2 = sW2b + buf * 4608;

        // stage1: acc1[16 x 32] = X(m16) @ W1chunk
        float acc1[4][4];
#pragma unroll
        for (int t = 0; t < 4; t++)
#pragma unroll
            for (int j = 0; j < 4; j++) acc1[t][j] = 0.f;
#pragma unroll
        for (int ks = 0; ks < 16; ks++) {
            int k0 = ks * 8;
            uint32_t a[4];
            ldA(a, sX, warp * 16, k0, 132, lane);
#pragma unroll
            for (int nt = 0; nt < 4; nt++) {
                uint32_t b[2];
                ldB(b, w1, nt * 8, k0, 132, lane);
                mma_tf32(acc1[nt], a, b[0], b[1]);
            }
        }
        // relu + tf32 -> sH (warp-private rows)
#pragma unroll
        for (int nt = 0; nt < 4; nt++) {
            int c0 = nt * 8 + lc;
            sH[(warp * 16 + lr) * 36 + c0] = f2tf(fmaxf(acc1[nt][0], 0.f));
            sH[(warp * 16 + lr) * 36 + c0 + 1] = f2tf(fmaxf(acc1[nt][1], 0.f));
            sH[(warp * 16 + lr + 8) * 36 + c0] = f2tf(fmaxf(acc1[nt][2], 0.f));
            sH[(warp * 16 + lr + 8) * 36 + c0 + 1] = f2tf(fmaxf(acc1[nt][3], 0.f));
        }
        __syncwarp();
        // stage2: acc2 += H(m16 x 32) @ W2chunk(n128)
#pragma unroll
        for (int ks = 0; ks < 4; ks++) {
            int k0 = ks * 8;
            uint32_t a[4];
            ldA(a, sH, warp * 16, k0, 36, lane);
#pragma unroll
            for (int nt = 0; nt < 16; nt++) {
                uint32_t b[2];
                ldB(b, w2, nt * 8, k0, 36, lane);
                mma_tf32(acc2[nt], a, b[0], b[1]);
            }
        }
        __syncwarp();  // sH reads done before next iter's stage1 overwrites
    }

    // epilogue: residual (exact, from g_t) + in-quad LN -> g_t
    size_t r0 = row0 + warp * 16 + lr, r1 = r0 + 8;
    float s0 = 0.f, q0 = 0.f, s1 = 0.f, q1 = 0.f;
#pragma unroll
    for (int nt = 0; nt < 16; nt++) {
        int col = nt * 8 + lc;
        float2 x0 = *(const float2*)&g_t[r0 * DM + col];
        float2 x1 = *(const float2*)&g_t[r1 * DM + col];
        acc2[nt][0] += x0.x; acc2[nt][1] += x0.y;
        acc2[nt][2] += x1.x; acc2[nt][3] += x1.y;
        s0 += acc2[nt][0] + acc2[nt][1];
        q0 += acc2[nt][0] * acc2[nt][0] + acc2[nt][1] * acc2[nt][1];
        s1 += acc2[nt][2] + acc2[nt][3];
        q1 += acc2[nt][2] * acc2[nt][2] + acc2[nt][3] * acc2[nt][3];
    }
#pragma unroll
    for (int o = 1; o <= 2; o <<= 1) {
        s0 += __shfl_xor_sync(0xffffffffu, s0, o);
        q0 += __shfl_xor_sync(0xffffffffu, q0, o);
        s1 += __shfl_xor_sync(0xffffffffu, s1, o);
        q1 += __shfl_xor_sync(0xffffffffu, q1, o);
    }
    float mu0 = s0 * (1.f / DM), rs0 = rsqrtf(q0 * (1.f / DM) - mu0 * mu0 + LNE);
    float mu1 = s1 * (1.f / DM), rs1 = rsqrtf(q1 * (1.f / DM) - mu1 * mu1 + LNE);
#pragma unroll
    for (int nt = 0; nt < 16; nt++) {
        int col = nt * 8 + lc;
        *(float2*)&g_t[r0 * DM + col] =
            make_float2((acc2[nt][0] - mu0) * rs0, (acc2[nt][1] - mu0) * rs0);
        *(float2*)&g_t[r1 * DM + col] =
            make_float2((acc2[nt][2] - mu1) * rs1, (acc2[nt][3] - mu1) * rs1);
    }
}

// ---------------- text: text/Kf/Vf/t0ln/Q0 ---------------------------------
__global__ void text_kernel(const float* __restrict__ g,
                            const float* __restrict__ Wtxt,
                            const float* __restrict__ Wkf,
                            const float* __restrict__ Wvf,
                            const float* __restrict__ Wq0) {
    __shared__ float sg[NG * GFD];
    __shared__ float sln[NG * DM];
    int tid = threadIdx.x;
    for (int i = tid; i < NG * GFD; i += 128) sg[i] = g[i];
    __syncthreads();
    int c = tid;
    float acc[NG];
#pragma unroll
    for (int r = 0; r < NG; r++) acc[r] = 0.f;
    for (int k = 0; k < GFD; k++) {
        float w = Wtxt[k * DM + c];
#pragma unroll
        for (int r = 0; r < NG; r++) acc[r] += sg[r * GFD + k] * w;
    }
    __syncthreads();
    float* st = sg;
#pragma unroll
    for (int r = 0; r < NG; r++) st[r * DM + c] = acc[r];
    __syncthreads();
    float a1[NG], a2[NG];
#pragma unroll
    for (int r = 0; r < NG; r++) { a1[r] = 0.f; a2[r] = 0.f; }
    for (int k = 0; k < DM; k++) {
        float w1 = Wkf[k * DM + c];
        float w2 = Wvf[k * DM + c];
#pragma unroll
        for (int r = 0; r < NG; r++) {
            float tv = st[r * DM + k];
            a1[r] += tv * w1;
            a2[r] += tv * w2;
        }
    }
#pragma unroll
    for (int r = 0; r < NG; r++) {
        g_Kf[r * DM + c] = a1[r];
        g_Vf[r * DM + c] = a2[r];
    }
    int warp = tid >> 5, lane = tid & 31;
#pragma unroll
    for (int i = 0; i < 4; i++) {
        int r = warp * 4 + i;
        float4 v = *(const float4*)&st[r * DM + lane * 4];
        float s = v.x + v.y + v.z + v.w;
        float q = v.x * v.x + v.y * v.y + v.z * v.z + v.w * v.w;
        s = warp_sum(s); q = warp_sum(q);
        float m = s * (1.f / DM);
        float rs = rsqrtf(q * (1.f / DM) - m * m + LNE);
        float4 o = {(v.x - m) * rs, (v.y - m) * rs, (v.z - m) * rs, (v.w - m) * rs};
        *(float4*)&sln[r * DM + lane * 4] = o;
        *(float4*)&g_t0ln[r * DM + lane * 4] = o;
    }
    __syncthreads();
    float aq[NG];
#pragma unroll
    for (int r = 0; r < NG; r++) aq[r] = 0.f;
    for (int k = 0; k < DM; k++) {
        float w = Wq0[k * DM + c];
#pragma unroll
        for (int r = 0; r < NG; r++) aq[r] += sln[r * DM + k] * w;
    }
#pragma unroll
    for (int r = 0; r < NG; r++) g_Q0[r * DM + c] = aq[r];
}

// ---------------- sliding-window cross attention ---------------------------
__global__ void __launch_bounds__(128) attn_kernel(int l) {
    extern __shared__ float sm[];
    float* sQ = sm;
    float* sR = sQ + NG * DM;
    float* sK = sR + NG * DM;
    float* sV = sK + LQ * DM;
    const float* Kl = g_K[l];
    const float* Vl = g_V[l];
    int tid = threadIdx.x;
    int f = blockIdx.x;
    size_t base = (size_t)f * NG * DM;
    int warp = tid >> 5, lane = tid & 31;
    if (l == 0) {
#pragma unroll
        for (int i = 0; i < 16; i++) {
            int e = i * 128 + tid;
            sQ[e] = g_Q0[e];
            sR[e] = g_t0ln[e];
        }
    } else {
#pragma unroll
        for (int i = 0; i < 16; i++) {
            int e = i * 128 + tid;
            sQ[e] = g_Qp[base + e];
        }
#pragma unroll
        for (int i = 0; i < 4; i++) {
            int r = warp * 4 + i;
            float4 v = *(const float4*)&g_t[base + r * DM + lane * 4];
            float s = v.x + v.y + v.z + v.w;
            float q = v.x * v.x + v.y * v.y + v.z * v.z + v.w * v.w;
            s = warp_sum(s); q = warp_sum(q);
            float m = s * (1.f / DM);
            float rs = rsqrtf(q * (1.f / DM) - m * m + LNE);
            float4 o = {(v.x - m) * rs, (v.y - m) * rs, (v.z - m) * rs, (v.w - m) * rs};
            *(float4*)&sR[r * DM + lane * 4] = o;
        }
    }
    for (int w = 0; w < LQ; w++) {
        int src = f - (LQ - 1) + w;
        float kv = 0.f, vv = 0.f;
        if (src >= 0) { kv = Kl[(size_t)src * DM + tid]; vv = Vl[(size_t)src * DM + tid]; }
        sK[w * DM + tid] = kv;
        sV[w * DM + tid] = vv;
    }
    __syncthreads();
    int h = tid >> 4, q = tid & 15;
    float4 qv[4];
#pragma unroll
    for (int d = 0; d < 4; d++) qv[d] = *(const float4*)&sQ[q * DM + h * 16 + d * 4];
    float sc[LQ];
    float mx = -1e30f;
#pragma unroll
    for (int k = 0; k < LQ; k++) {
        const float4* kr = (const float4*)&sK[k * DM + h * 16];
        float s = 0.f;
#pragma unroll
        for (int d = 0; d < 4; d++) {
            float4 kk = kr[d];
            s += qv[d].x * kk.x + qv[d].y * kk.y + qv[d].z * kk.z + qv[d].w * kk.w;
        }
        s *= 0.25f;
        sc[k] = s;
        mx = fmaxf(mx, s);
    }
    float sum = 0.f;
#pragma unroll
    for (int k = 0; k < LQ; k++) {
        float e = __expf(sc[k] - mx);
        sc[k] = e;
        sum += e;
    }
    float inv = 1.f / sum;
    float4 ctx[4];
#pragma unroll
    for (int d = 0; d < 4; d++) ctx[d] = make_float4(0.f, 0.f, 0.f, 0.f);
#pragma unroll
    for (int k = 0; k < LQ; k++) {
        float p = sc[k];
        const float4* vr = (const float4*)&sV[k * DM + h * 16];
#pragma unroll
        for (int d = 0; d < 4; d++) {
            float4 vv = vr[d];
            ctx[d].x += p * vv.x; ctx[d].y += p * vv.y;
            ctx[d].z += p * vv.z; ctx[d].w += p * vv.w;
        }
    }
    __syncthreads();
#pragma unroll
    for (int d = 0; d < 4; d++) {
        float4 o = {ctx[d].x * inv, ctx[d].y * inv, ctx[d].z * inv, ctx[d].w * inv};
        *(float4*)&sQ[q * DM + h * 16 + d * 4] = o;
    }
    __syncthreads();
#pragma unroll
    for (int i = 0; i < 4; i++) {
        int r = warp * 4 + i;
        float vals[4];
        float s = 0.f, qq = 0.f;
#pragma unroll
        for (int j = 0; j < 4; j++) {
            int cc = lane + 32 * j;
            float v = sQ[r * DM + cc] + sR[r * DM + cc];
            vals[j] = v;
            s += v;
            qq += v * v;
        }
        s = warp_sum(s); qq = warp_sum(qq);
        float m = s * (1.f / DM);
        float rs = rsqrtf(qq * (1.f / DM) - m * m + LNE);
#pragma unroll
        for (int j = 0; j < 4; j++)
            g_t[base + r * DM + lane + 32 * j] = (vals[j] - m) * rs;
    }
}

// ---------------- final single-head attention ------------------------------
__global__ void final_kernel(float* __restrict__ out) {
    __shared__ float st[NG * DM];
    __shared__ float sQ[NG * DM];
    __shared__ float sKf[NG * 132];
    __shared__ float sVf[NG * DM];
    __shared__ float sS[NG][NG + 1];
    int tid = threadIdx.x;
    int f = blockIdx.x;
    size_t base = (size_t)f * NG * DM;
#pragma unroll
    for (int i = 0; i < 8; i++) {
        int e = i * 256 + tid, r = e >> 7, c = e & 127;
        st[e] = g_t[base + e];
        sQ[e] = g_Qp[base + e];
        sKf[r * 132 + c] = g_Kf[e];
        sVf[e] = g_Vf[e];
    }
    __syncthreads();
    {
        int qr = tid >> 4, kr = tid & 15;
        float a = 0.f;
        for (int k = 0; k < DM; k++) a += sQ[qr * DM + k] * sKf[kr * 132 + k];
        sS[qr][kr] = a * 0.08838834764831843f;
    }
    __syncthreads();
    if (tid < NG) {
        float mx = -1e30f;
#pragma unroll
        for (int k = 0; k < NG; k++) mx = fmaxf(mx, sS[tid][k]);
        float sum = 0.f;
#pragma unroll
        for (int k = 0; k < NG; k++) {
            float e = __expf(sS[tid][k] - mx);
            sS[tid][k] = e;
            sum += e;
        }
        float inv = 1.f / sum;
#pragma unroll
        for (int k = 0; k < NG; k++) sS[tid][k] *= inv;
    }
    __syncthreads();
#pragma unroll
    for (int i = 0; i < 8; i++) {
        int e = i * 256 + tid, r = e >> 7, c = e & 127;
        float a = 0.f;
#pragma unroll
        for (int k = 0; k < NG; k++) a += sS[r][k] * sVf[k * DM + c];
        sQ[e] = a + st[e];
    }
    __syncthreads();
    int warp = tid >> 5, lane = tid & 31;
#pragma unroll
    for (int i = 0; i < 2; i++) {
        int r = warp * 2 + i;
        float4 v0 = *(const float4*)&sQ[r * DM + lane * 4];
        float s = v0.x + v0.y + v0.z + v0.w;
        float q = v0.x * v0.x + v0.y * v0.y + v0.z * v0.z + v0.w * v0.w;
        s = warp_sum(s); q = warp_sum(q);
        float m = s * (1.f / DM);
        float rs = rsqrtf(q * (1.f / DM) - m * m + LNE);
        float4 o = {(v0.x - m) * rs, (v0.y - m) * rs, (v0.z - m) * rs, (v0.w - m) * rs};
        *(float4*)&out[base + r * DM + lane * 4] = o;
    }
}

extern "C" void kernel_launch(void* const* d_in, const int* in_sizes, int n_in,
                              void* d_out, int out_size) {
    const float* g    = (const float*)d_in[0];
    const float* LF   = (const float*)d_in[1];
    const float* Wvis = (const float*)d_in[2];
    const float* Wtxt = (const float*)d_in[3];
    const float* Wq   = (const float*)d_in[4];
    const float* Wk   = (const float*)d_in[5];
    const float* Wv   = (const float*)d_in[6];
    const float* W1   = (const float*)d_in[7];
    const float* W2   = (const float*)d_in[8];
    const float* Wqf  = (const float*)d_in[9];
    const float* Wkf  = (const float*)d_in[10];
    const float* Wvf  = (const float*)d_in[11];
    float* out = (float*)d_out;

    const int ATTN_SMEM = (2 * NG * DM + 2 * LQ * DM) * 4;     // 81920
    const int GEMM_SMEM = (64 * 132 + 128 * 132) * 4;          // 101376
    const int VIS_SMEM  = (64 * 68 + 128 * 68) * 4;            // 52224
    cudaFuncSetAttribute(attn_kernel, cudaFuncAttributeMaxDynamicSharedMemorySize, ATTN_SMEM);
    cudaFuncSetAttribute(kv_kernel, cudaFuncAttributeMaxDynamicSharedMemorySize, GEMM_SMEM);
    cudaFuncSetAttribute(qproj_kernel, cudaFuncAttributeMaxDynamicSharedMemorySize, GEMM_SMEM);
    cudaFuncSetAttribute(visual_mma, cudaFuncAttributeMaxDynamicSharedMemorySize, VIS_SMEM);
    cudaFuncSetAttribute(ffn_tf32, cudaFuncAttributeMaxDynamicSharedMemorySize, FFN_SMEM);

    convert_kernel<<<dim3(1024, 12), 256>>>(W1, W2, Wq, Wk, Wv, Wqf, Wvis);   // 0
    text_kernel<<<1, 128>>>(g, Wtxt, Wkf, Wvf, Wq);                           // 1
    visual_mma<<<TFR / 64, 256, VIS_SMEM>>>(LF);                              // 2
    kv_kernel<<<dim3(TFR / 64, 4), 256, GEMM_SMEM>>>();                       // 3
    attn_kernel<<<TFR, 128, ATTN_SMEM>>>(0);                                  // 4
    ffn_tf32<<<NTOK / 128, 256, FFN_SMEM>>>(0);                               // 5 <- profiled
    qproj_kernel<<<NTOK / 64, 256, GEMM_SMEM>>>(0);                           // 6
    attn_kernel<<<TFR, 128, ATTN_SMEM>>>(1);                                  // 7
    ffn_tf32<<<NTOK / 128, 256, FFN_SMEM>>>(1);                               // 8
    qproj_kernel<<<NTOK / 64, 256, GEMM_SMEM>>>(1);                           // 9
    final_kernel<<<TFR, 256>>>(out);                                          // 10
}

// round 8
// speedup vs baseline: 1.0124x; 1.0124x over previous
#include <cuda_runtime.h>
#include <cuda_bf16.h>
#include <cstdint>

#define TFR 4096
#define DM 128
#define LQ 64
#define NG 16
#define FD 2048
#define GFD 512
#define NTOK (TFR * NG)
#define LNE 1e-5f

// ---------------- device-global scratch ------------------------------------
__device__ float g_lnvis[TFR * DM];
__device__ float g_t0ln[NG * DM];
__device__ float g_Q0[NG * DM];
__device__ float g_Kf[NG * DM];
__device__ float g_Vf[NG * DM];
__device__ float g_K[2][TFR * DM];
__device__ float g_V[2][TFR * DM];
__device__ float g_t[NTOK * DM];
__device__ float g_Qp[NTOK * DM];

// transposed ([n][k]) weights, tf32 bit patterns
__device__ uint32_t g_W1t[2][FD * DM];   // [2048][128]
__device__ uint32_t g_W2t[2][DM * FD];   // [128][2048]
__device__ uint32_t g_Wqt[2][DM * DM];
__device__ uint32_t g_Wkt[2][DM * DM];
__device__ uint32_t g_Wvt[2][DM * DM];
__device__ uint32_t g_Wqft[DM * DM];
__device__ uint32_t g_Wvist[DM * FD];    // [128][2048]

__device__ __forceinline__ float warp_sum(float v) {
#pragma unroll
    for (int o = 16; o > 0; o >>= 1) v += __shfl_xor_sync(0xffffffffu, v, o);
    return v;
}
__device__ __forceinline__ uint32_t cvta_s(const void* p) {
    return (uint32_t)__cvta_generic_to_shared(p);
}
__device__ __forceinline__ uint32_t f2tf(float v) {
    uint32_t r;
    asm("cvt.rna.tf32.f32 %0, %1;" : "=r"(r) : "f"(v));
    return r;
}
__device__ __forceinline__ void mma_tf32(float c[4], const uint32_t a[4],
                                         uint32_t b0, uint32_t b1) {
    asm volatile(
        "mma.sync.aligned.m16n8k8.row.col.f32.tf32.tf32.f32 "
        "{%0,%1,%2,%3},{%4,%5,%6,%7},{%8,%9},{%0,%1,%2,%3};"
        : "+f"(c[0]), "+f"(c[1]), "+f"(c[2]), "+f"(c[3])
        : "r"(a[0]), "r"(a[1]), "r"(a[2]), "r"(a[3]), "r"(b0), "r"(b1));
}
// A fragment m16k8 from [m][k] smem (tf32 bits)
__device__ __forceinline__ void ldA(uint32_t a[4], const uint32_t* s, int m0,
                                    int k0, int stride, int lane) {
    int r = m0 + (lane >> 2), c = k0 + (lane & 3);
    a[0] = s[r * stride + c];
    a[1] = s[(r + 8) * stride + c];
    a[2] = s[r * stride + c + 4];
    a[3] = s[(r + 8) * stride + c + 4];
}
// B fragment k8n8 from [n][k] smem
__device__ __forceinline__ void ldB(uint32_t b[2], const uint32_t* s, int n0,
                                    int k0, int stride, int lane) {
    int n = n0 + (lane >> 2), c = k0 + (lane & 3);
    b[0] = s[n * stride + c];
    b[1] = s[n * stride + c + 4];
}
#define CP16(dst, src) \
    asm volatile("cp.async.cg.shared.global [%0], [%1], 16;" :: "r"(dst), "l"(src))
#define CP_COMMIT() asm volatile("cp.async.commit_group;" ::: "memory")
#define CP_WAIT1() asm volatile("cp.async.wait_group 1;" ::: "memory")

// ---------------- fused weight conversion (one launch) ---------------------
__global__ void convert_kernel(const float* W1, const float* W2, const float* Wq,
                               const float* Wk, const float* Wv, const float* Wqf,
                               const float* Wvis) {
    int seg = blockIdx.y;
    const float* src;
    uint32_t* dst;
    int K, N;
    switch (seg) {
        case 0:  src = W1;                 dst = g_W1t[0]; K = DM; N = FD; break;
        case 1:  src = W1 + (size_t)DM*FD; dst = g_W1t[1]; K = DM; N = FD; break;
        case 2:  src = W2;                 dst = g_W2t[0]; K = FD; N = DM; break;
        case 3:  src = W2 + (size_t)FD*DM; dst = g_W2t[1]; K = FD; N = DM; break;
        case 4:  src = Wq;                 dst = g_Wqt[0]; K = DM; N = DM; break;
        case 5:  src = Wq + DM*DM;         dst = g_Wqt[1]; K = DM; N = DM; break;
        case 6:  src = Wk;                 dst = g_Wkt[0]; K = DM; N = DM; break;
        case 7:  src = Wk + DM*DM;         dst = g_Wkt[1]; K = DM; N = DM; break;
        case 8:  src = Wv;                 dst = g_Wvt[0]; K = DM; N = DM; break;
        case 9:  src = Wv + DM*DM;         dst = g_Wvt[1]; K = DM; N = DM; break;
        case 10: src = Wqf;                dst = g_Wqft;   K = DM; N = DM; break;
        default: src = Wvis;               dst = g_Wvist;  K = FD; N = DM; break;
    }
    int idx = blockIdx.x * 256 + threadIdx.x;
    if (idx >= K * N) return;
    int k = idx / N, n = idx - k * N;
    dst[(size_t)n * K + k] = f2tf(src[idx]);
}

// ---------------- generic 64-row GEMM, K=128, tf32 single pass --------------
__device__ __forceinline__ void gemm128_core(const float* A, float* C,
                                             const uint32_t* Bt, int a_ln,
                                             uint32_t* smu) {
    uint32_t* sA = smu;              // [64][132]
    uint32_t* sB = smu + 64 * 132;   // [128][132]
    int tid = threadIdx.x, lane = tid & 31, warp = tid >> 5;
    size_t row0 = (size_t)blockIdx.x * 64;

#pragma unroll
    for (int i = 0; i < 8; i++) {
        int r = warp * 8 + i;
        float4 v = *(const float4*)&A[(row0 + r) * DM + lane * 4];
        if (a_ln) {
            float s = v.x + v.y + v.z + v.w;
            float q = v.x * v.x + v.y * v.y + v.z * v.z + v.w * v.w;
            s = warp_sum(s); q = warp_sum(q);
            float m = s * (1.f / DM);
            float rs = rsqrtf(q * (1.f / DM) - m * m + LNE);
            v.x = (v.x - m) * rs; v.y = (v.y - m) * rs;
            v.z = (v.z - m) * rs; v.w = (v.w - m) * rs;
        }
        uint4 t;
        t.x = f2tf(v.x); t.y = f2tf(v.y); t.z = f2tf(v.z); t.w = f2tf(v.w);
        *(uint4*)&sA[r * 132 + lane * 4] = t;
    }
#pragma unroll
    for (int u = 0; u < 16; u++) {
        int e = u * 256 + tid;
        int n = e >> 5, kk = (e & 31) * 4;
        *(uint4*)&sB[n * 132 + kk] = *(const uint4*)&Bt[n * DM + kk];
    }
    __syncthreads();

    int m0 = (warp >> 1) * 16, n0 = (warp & 1) * 64;
    float acc[8][4];
#pragma unroll
    for (int t = 0; t < 8; t++)
#pragma unroll
        for (int j = 0; j < 4; j++) acc[t][j] = 0.f;

#pragma unroll
    for (int ks = 0; ks < 16; ks++) {
        int k0 = ks * 8;
        uint32_t a[4];
        ldA(a, sA, m0, k0, 132, lane);
#pragma unroll
        for (int nt = 0; nt < 8; nt++) {
            uint32_t b[2];
            ldB(b, sB, n0 + nt * 8, k0, 132, lane);
            mma_tf32(acc[nt], a, b[0], b[1]);
        }
    }
    int r = m0 + (lane >> 2), cb = (lane & 3) * 2;
#pragma unroll
    for (int t = 0; t < 8; t++) {
        int col = n0 + t * 8 + cb;
        *(float2*)&C[(row0 + r) * DM + col] = make_float2(acc[t][0], acc[t][1]);
        *(float2*)&C[(row0 + r + 8) * DM + col] = make_float2(acc[t][2], acc[t][3]);
    }
}

__global__ void __launch_bounds__(256) kv_kernel() {
    extern __shared__ uint32_t smg[];
    int s = blockIdx.y;
    const uint32_t* Bt = (s == 0) ? g_Wkt[0] : (s == 1) ? g_Wvt[0]
                       : (s == 2) ? g_Wkt[1] : g_Wvt[1];
    float* C = (s == 0) ? g_K[0] : (s == 1) ? g_V[0] : (s == 2) ? g_K[1] : g_V[1];
    gemm128_core(g_lnvis, C, Bt, 0, smg);
}
__global__ void __launch_bounds__(256) qproj_kernel(int mode) {
    extern __shared__ uint32_t smg[];
    if (mode == 0)
        gemm128_core(g_t, g_Qp, g_Wqt[1], 1, smg);
    else
        gemm128_core(g_t, g_Qp, g_Wqft, 0, smg);
}

// ---------------- visual: lnvis = LN(LF @ Wvis), tf32, K=2048 ---------------
__global__ void __launch_bounds__(256) visual_mma(const float* __restrict__ LF) {
    extern __shared__ uint32_t smv[];
    uint32_t* sA = smv;              // [64][68]
    uint32_t* sB = smv + 64 * 68;    // [128][68]
    float* sY = (float*)smv;         // [64][132] alias (after MMA loop)
    int tid = threadIdx.x, lane = tid & 31, warp = tid >> 5;
    size_t row0 = (size_t)blockIdx.x * 64;
    int m0 = (warp >> 1) * 16, n0 = (warp & 1) * 64;
    float acc[8][4];
#pragma unroll
    for (int t = 0; t < 8; t++)
#pragma unroll
        for (int j = 0; j < 4; j++) acc[t][j] = 0.f;

    for (int kc = 0; kc < FD; kc += 64) {
#pragma unroll
        for (int u = 0; u < 4; u++) {
            int e = u * 256 + tid;
            int r = e >> 4, c4 = (e & 15) * 4;
            float4 v = *(const float4*)&LF[(row0 + r) * FD + kc + c4];
            uint4 t;
            t.x = f2tf(v.x); t.y = f2tf(v.y); t.z = f2tf(v.z); t.w = f2tf(v.w);
            *(uint4*)&sA[r * 68 + c4] = t;
        }
#pragma unroll
        for (int u = 0; u < 8; u++) {
            int e = u * 256 + tid;
            int n = e >> 4, kk = (e & 15) * 4;
            *(uint4*)&sB[n * 68 + kk] = *(const uint4*)&g_Wvist[(size_t)n * FD + kc + kk];
        }
        __syncthreads();
#pragma unroll
        for (int ks = 0; ks < 8; ks++) {
            int k0 = ks * 8;
            uint32_t a[4];
            ldA(a, sA, m0, k0, 68, lane);
#pragma unroll
            for (int nt = 0; nt < 8; nt++) {
                uint32_t b[2];
                ldB(b, sB, n0 + nt * 8, k0, 68, lane);
                mma_tf32(acc[nt], a, b[0], b[1]);
            }
        }
        __syncthreads();
    }
    int r = m0 + (lane >> 2), cb = (lane & 3) * 2;
#pragma unroll
    for (int t = 0; t < 8; t++) {
        int col = n0 + t * 8 + cb;
        sY[r * 132 + col] = acc[t][0];
        sY[r * 132 + col + 1] = acc[t][1];
        sY[(r + 8) * 132 + col] = acc[t][2];
        sY[(r + 8) * 132 + col + 1] = acc[t][3];
    }
    __syncthreads();
#pragma unroll
    for (int i = 0; i < 8; i++) {
        int rr = warp * 8 + i;
        float4 v = *(const float4*)&sY[rr * 132 + lane * 4];
        float s = v.x + v.y + v.z + v.w;
        float q = v.x * v.x + v.y * v.y + v.z * v.z + v.w * v.w;
        s = warp_sum(s); q = warp_sum(q);
        float m = s * (1.f / DM);
        float rs = rsqrtf(q * (1.f / DM) - m * m + LNE);
        float4 o = {(v.x - m) * rs, (v.y - m) * rs, (v.z - m) * rs, (v.w - m) * rs};
        *(float4*)&g_lnvis[(row0 + rr) * DM + lane * 4] = o;
    }
}

// ---------------- FFN: tf32, 512 threads (16 warps), cp.async dbl-buf ------
// smem u32: sX[128][132]=16896 | W1 2x[32][132] @16896 | W2 2x[128][36] @25344
//           H[128][36] @34560  -> 39168 u32 = 156672 B
#define FFN_SMEM (39168 * 4)
#define NCH 64

__global__ void __launch_bounds__(512) ffn_tf32(int l) {
    extern __shared__ uint32_t smf[];
    uint32_t* sX = smf;               // [128][132]
    uint32_t* sH = smf + 34560;       // [128][36]
    const uint32_t* W1 = g_W1t[l];
    const uint32_t* W2 = g_W2t[l];
    int tid = threadIdx.x, lane = tid & 31, warp = tid >> 5;
    int wm = warp >> 1, wn = warp & 1;
    int m0 = wm * 16;
    size_t row0 = (size_t)blockIdx.x * 128;
    uint32_t sb = cvta_s(smf);

    // prologue: LN + tf32 X  (16 warps x 8 rows)
#pragma unroll
    for (int i = 0; i < 8; i++) {
        int r = warp * 8 + i;
        float4 v = *(const float4*)&g_t[(row0 + r) * DM + lane * 4];
        float s = v.x + v.y + v.z + v.w;
        float q = v.x * v.x + v.y * v.y + v.z * v.z + v.w * v.w;
        s = warp_sum(s); q = warp_sum(q);
        float m = s * (1.f / DM);
        float rs = rsqrtf(q * (1.f / DM) - m * m + LNE);
        uint4 t;
        t.x = f2tf((v.x - m) * rs); t.y = f2tf((v.y - m) * rs);
        t.z = f2tf((v.z - m) * rs); t.w = f2tf((v.w - m) * rs);
        *(uint4*)&sX[r * 132 + lane * 4] = t;
    }
    // preload chunk 0 into buf 0
    {
        uint32_t w1d = sb + 16896 * 4, w2d = sb + 25344 * 4;
#pragma unroll
        for (int u = 0; u < 2; u++) {
            int e = u * 512 + tid;
            int n = e >> 5, kk = (e & 31) * 4;
            CP16(w1d + (n * 132 + kk) * 4, W1 + (size_t)n * DM + kk);
        }
#pragma unroll
        for (int u = 0; u < 2; u++) {
            int e = u * 512 + tid;
            int n = e >> 3, kk = (e & 7) * 4;
            CP16(w2d + (n * 36 + kk) * 4, W2 + (size_t)n * FD + kk);
        }
        CP_COMMIT();
    }

    float acc2[8][4];
#pragma unroll
    for (int t = 0; t < 8; t++)
#pragma unroll
        for (int j = 0; j < 4; j++) acc2[t][j] = 0.f;

    int lr = lane >> 2, lc = 2 * (lane & 3);
    for (int i = 0; i < NCH; i++) {
        int buf = i & 1, nb = buf ^ 1;
        __syncthreads();  // prev-iter reads of buffer nb and of sH complete
        if (i + 1 < NCH) {
            uint32_t w1d = sb + (16896 + nb * 4224) * 4;
            uint32_t w2d = sb + (25344 + nb * 4608) * 4;
            const uint32_t* W1s = W1 + (size_t)(i + 1) * 32 * DM;
#pragma unroll
            for (int u = 0; u < 2; u++) {
                int e = u * 512 + tid;
                int n = e >> 5, kk = (e & 31) * 4;
                CP16(w1d + (n * 132 + kk) * 4, W1s + (size_t)n * DM + kk);
            }
#pragma unroll
            for (int u = 0; u < 2; u++) {
                int e = u * 512 + tid;
                int n = e >> 3, kk = (e & 7) * 4;
                CP16(w2d + (n * 36 + kk) * 4, W2 + (size_t)n * FD + (i + 1) * 32 + kk);
            }
        }
        CP_COMMIT();
        CP_WAIT1();
        __syncthreads();
        const uint32_t* w1 = smf + 16896 + buf * 4224;
        const uint32_t* w2 = smf + 25344 + buf * 4608;

        // stage1: acc1 = X(m16) @ W1chunk(n16 of 32, per wn)
        float acc1[2][4];
#pragma unroll
        for (int t = 0; t < 2; t++)
#pragma unroll
            for (int j = 0; j < 4; j++) acc1[t][j] = 0.f;
#pragma unroll
        for (int ks = 0; ks < 16; ks++) {
            int k0 = ks * 8;
            uint32_t a[4];
            ldA(a, sX, m0, k0, 132, lane);
#pragma unroll
            for (int nt = 0; nt < 2; nt++) {
                uint32_t b[2];
                ldB(b, w1, wn * 16 + nt * 8, k0, 132, lane);
                mma_tf32(acc1[nt], a, b[0], b[1]);
            }
        }
        // relu + tf32 -> sH
#pragma unroll
        for (int nt = 0; nt < 2; nt++) {
            int c0 = wn * 16 + nt * 8 + lc;
            sH[(m0 + lr) * 36 + c0] = f2tf(fmaxf(acc1[nt][0], 0.f));
            sH[(m0 + lr) * 36 + c0 + 1] = f2tf(fmaxf(acc1[nt][1], 0.f));
            sH[(m0 + lr + 8) * 36 + c0] = f2tf(fmaxf(acc1[nt][2], 0.f));
            sH[(m0 + lr + 8) * 36 + c0 + 1] = f2tf(fmaxf(acc1[nt][3], 0.f));
        }
        __syncthreads();  // H visible across wn pair
        // stage2: acc2 += H(m16 x 32) @ W2chunk(n64 per wn)
#pragma unroll
        for (int ks = 0; ks < 4; ks++) {
            int k0 = ks * 8;
            uint32_t a[4];
            ldA(a, sH, m0, k0, 36, lane);
#pragma unroll
            for (int nt = 0; nt < 8; nt++) {
                uint32_t b[2];
                ldB(b, w2, wn * 64 + nt * 8, k0, 36, lane);
                mma_tf32(acc2[nt], a, b[0], b[1]);
            }
        }
    }
    __syncthreads();

    // epilogue: residual (exact, from g_t) -> sY, then row LN -> g_t
    float* sY = (float*)(smf + 16896);  // [128][132] overwrites W bufs
#pragma unroll
    for (int nt = 0; nt < 8; nt++) {
        int col = wn * 64 + nt * 8 + lc;
        int r0 = m0 + lr, r1 = m0 + lr + 8;
        float2 x0 = *(const float2*)&g_t[(row0 + r0) * DM + col];
        float2 x1 = *(const float2*)&g_t[(row0 + r1) * DM + col];
        sY[r0 * 132 + col] = acc2[nt][0] + x0.x;
        sY[r0 * 132 + col + 1] = acc2[nt][1] + x0.y;
        sY[r1 * 132 + col] = acc2[nt][2] + x1.x;
        sY[r1 * 132 + col + 1] = acc2[nt][3] + x1.y;
    }
    __syncthreads();
#pragma unroll
    for (int i = 0; i < 8; i++) {
        int r = warp * 8 + i;
        float4 v = *(const float4*)&sY[r * 132 + lane * 4];
        float s = v.x + v.y + v.z + v.w;
        float q = v.x * v.x + v.y * v.y + v.z * v.z + v.w * v.w;
        s = warp_sum(s); q = warp_sum(q);
        float m = s * (1.f / DM);
        float rs = rsqrtf(q * (1.f / DM) - m * m + LNE);
        float4 o = {(v.x - m) * rs, (v.y - m) * rs, (v.z - m) * rs, (v.w - m) * rs};
        *(float4*)&g_t[(row0 + r) * DM + lane * 4] = o;
    }
}

// ---------------- text: text/Kf/Vf/t0ln/Q0 ---------------------------------
__global__ void text_kernel(const float* __restrict__ g,
                            const float* __restrict__ Wtxt,
                            const float* __restrict__ Wkf,
                            const float* __restrict__ Wvf,
                            const float* __restrict__ Wq0) {
    __shared__ float sg[NG * GFD];
    __shared__ float sln[NG * DM];
    int tid = threadIdx.x;
    for (int i = tid; i < NG * GFD; i += 128) sg[i] = g[i];
    __syncthreads();
    int c = tid;
    float acc[NG];
#pragma unroll
    for (int r = 0; r < NG; r++) acc[r] = 0.f;
    for (int k = 0; k < GFD; k++) {
        float w = Wtxt[k * DM + c];
#pragma unroll
        for (int r = 0; r < NG; r++) acc[r] += sg[r * GFD + k] * w;
    }
    __syncthreads();
    float* st = sg;
#pragma unroll
    for (int r = 0; r < NG; r++) st[r * DM + c] = acc[r];
    __syncthreads();
    float a1[NG], a2[NG];
#pragma unroll
    for (int r = 0; r < NG; r++) { a1[r] = 0.f; a2[r] = 0.f; }
    for (int k = 0; k < DM; k++) {
        float w1 = Wkf[k * DM + c];
        float w2 = Wvf[k * DM + c];
#pragma unroll
        for (int r = 0; r < NG; r++) {
            float tv = st[r * DM + k];
            a1[r] += tv * w1;
            a2[r] += tv * w2;
        }
    }
#pragma unroll
    for (int r = 0; r < NG; r++) {
        g_Kf[r * DM + c] = a1[r];
        g_Vf[r * DM + c] = a2[r];
    }
    int warp = tid >> 5, lane = tid & 31;
#pragma unroll
    for (int i = 0; i < 4; i++) {
        int r = warp * 4 + i;
        float4 v = *(const float4*)&st[r * DM + lane * 4];
        float s = v.x + v.y + v.z + v.w;
        float q = v.x * v.x + v.y * v.y + v.z * v.z + v.w * v.w;
        s = warp_sum(s); q = warp_sum(q);
        float m = s * (1.f / DM);
        float rs = rsqrtf(q * (1.f / DM) - m * m + LNE);
        float4 o = {(v.x - m) * rs, (v.y - m) * rs, (v.z - m) * rs, (v.w - m) * rs};
        *(float4*)&sln[r * DM + lane * 4] = o;
        *(float4*)&g_t0ln[r * DM + lane * 4] = o;
    }
    __syncthreads();
    float aq[NG];
#pragma unroll
    for (int r = 0; r < NG; r++) aq[r] = 0.f;
    for (int k = 0; k < DM; k++) {
        float w = Wq0[k * DM + c];
#pragma unroll
        for (int r = 0; r < NG; r++) aq[r] += sln[r * DM + k] * w;
    }
#pragma unroll
    for (int r = 0; r < NG; r++) g_Q0[r * DM + c] = aq[r];
}

// ---------------- sliding-window cross attention: 2 frames / block ---------
// smem floats: sQ[2][2048] | sR[2][2048] | sK[65*128] | sV[65*128]
#define ATTN_SMEM ((4096 + 4096 + 2 * 65 * 128) * 4)

__global__ void __launch_bounds__(256) attn_kernel(int l) {
    extern __shared__ float sm[];
    float* sK = sm + 8192;
    float* sV = sK + 65 * 128;
    const float* Kl = g_K[l];
    const float* Vl = g_V[l];
    int tid = threadIdx.x;
    int grp = tid >> 7, gt = tid & 127;
    int f0 = blockIdx.x * 2;
    int f = f0 + grp;
    size_t base = (size_t)f * NG * DM;
    float* mQ = sm + grp * 2048;
    float* mR = sm + 4096 + grp * 2048;
    int gw = gt >> 5, lane = gt & 31;

    if (l == 0) {
#pragma unroll
        for (int i = 0; i < 16; i++) {
            int e = i * 128 + gt;
            mQ[e] = g_Q0[e];
            mR[e] = g_t0ln[e];
        }
    } else {
#pragma unroll
        for (int i = 0; i < 16; i++) {
            int e = i * 128 + gt;
            mQ[e] = g_Qp[base + e];
        }
#pragma unroll
        for (int i = 0; i < 4; i++) {
            int r = gw * 4 + i;
            float4 v = *(const float4*)&g_t[base + r * DM + lane * 4];
            float s = v.x + v.y + v.z + v.w;
            float q = v.x * v.x + v.y * v.y + v.z * v.z + v.w * v.w;
            s = warp_sum(s); q = warp_sum(q);
            float m = s * (1.f / DM);
            float rs = rsqrtf(q * (1.f / DM) - m * m + LNE);
            float4 o = {(v.x - m) * rs, (v.y - m) * rs, (v.z - m) * rs, (v.w - m) * rs};
            *(float4*)&mR[r * DM + lane * 4] = o;
        }
    }
    // union K/V window: rows w=0..64 are src = f0-63+w (both frames covered)
    for (int idx = tid; idx < 65 * 128; idx += 256) {
        int w = idx >> 7;
        int src = f0 - (LQ - 1) + w;
        float kv = 0.f, vv = 0.f;
        if (src >= 0) {
            kv = Kl[(size_t)src * DM + (idx & 127)];
            vv = Vl[(size_t)src * DM + (idx & 127)];
        }
        sK[idx] = kv;
        sV[idx] = vv;
    }
    __syncthreads();
    int h = gt >> 4, q = gt & 15;
    float4 qv[4];
#pragma unroll
    for (int d = 0; d < 4; d++) qv[d] = *(const float4*)&mQ[q * DM + h * 16 + d * 4];
    float sc[LQ];
    float mx = -1e30f;
#pragma unroll
    for (int k = 0; k < LQ; k++) {
        const float4* kr = (const float4*)&sK[(k + grp) * DM + h * 16];
        float s = 0.f;
#pragma unroll
        for (int d = 0; d < 4; d++) {
            float4 kk = kr[d];
            s += qv[d].x * kk.x + qv[d].y * kk.y + qv[d].z * kk.z + qv[d].w * kk.w;
        }
        s *= 0.25f;
        sc[k] = s;
        mx = fmaxf(mx, s);
    }
    float sum = 0.f;
#pragma unroll
    for (int k = 0; k < LQ; k++) {
        float e = __expf(sc[k] - mx);
        sc[k] = e;
        sum += e;
    }
    float inv = 1.f / sum;
    float4 ctx[4];
#pragma unroll
    for (int d = 0; d < 4; d++) ctx[d] = make_float4(0.f, 0.f, 0.f, 0.f);
#pragma unroll
    for (int k = 0; k < LQ; k++) {
        float p = sc[k];
        const float4* vr = (const float4*)&sV[(k + grp) * DM + h * 16];
#pragma unroll
        for (int d = 0; d < 4; d++) {
            float4 vv = vr[d];
            ctx[d].x += p * vv.x; ctx[d].y += p * vv.y;
            ctx[d].z += p * vv.z; ctx[d].w += p * vv.w;
        }
    }
    __syncthreads();
#pragma unroll
    for (int d = 0; d < 4; d++) {
        float4 o = {ctx[d].x * inv, ctx[d].y * inv, ctx[d].z * inv, ctx[d].w * inv};
        *(float4*)&mQ[q * DM + h * 16 + d * 4] = o;
    }
    __syncthreads();
#pragma unroll
    for (int i = 0; i < 4; i++) {
        int r = gw * 4 + i;
        float vals[4];
        float s = 0.f, qq = 0.f;
#pragma unroll
        for (int j = 0; j < 4; j++) {
            int cc = lane + 32 * j;
            float v = mQ[r * DM + cc] + mR[r * DM + cc];
            vals[j] = v;
            s += v;
            qq += v * v;
        }
        s = warp_sum(s); qq = warp_sum(qq);
        float m = s * (1.f / DM);
        float rs = rsqrtf(qq * (1.f / DM) - m * m + LNE);
#pragma unroll
        for (int j = 0; j < 4; j++)
            g_t[base + r * DM + lane + 32 * j] = (vals[j] - m) * rs;
    }
}

// ---------------- final single-head attention ------------------------------
__global__ void final_kernel(float* __restrict__ out) {
    __shared__ float st[NG * DM];
    __shared__ float sQ[NG * DM];
    __shared__ float sKf[NG * 132];
    __shared__ float sVf[NG * DM];
    __shared__ float sS[NG][NG + 1];
    int tid = threadIdx.x;
    int f = blockIdx.x;
    size_t base = (size_t)f * NG * DM;
#pragma unroll
    for (int i = 0; i < 8; i++) {
        int e = i * 256 + tid, r = e >> 7, c = e & 127;
        st[e] = g_t[base + e];
        sQ[e] = g_Qp[base + e];
        sKf[r * 132 + c] = g_Kf[e];
        sVf[e] = g_Vf[e];
    }
    __syncthreads();
    {
        int qr = tid >> 4, kr = tid & 15;
        float a = 0.f;
        for (int k = 0; k < DM; k++) a += sQ[qr * DM + k] * sKf[kr * 132 + k];
        sS[qr][kr] = a * 0.08838834764831843f;
    }
    __syncthreads();
    if (tid < NG) {
        float mx = -1e30f;
#pragma unroll
        for (int k = 0; k < NG; k++) mx = fmaxf(mx, sS[tid][k]);
        float sum = 0.f;
#pragma unroll
        for (int k = 0; k < NG; k++) {
            float e = __expf(sS[tid][k] - mx);
            sS[tid][k] = e;
            sum += e;
        }
        float inv = 1.f / sum;
#pragma unroll
        for (int k = 0; k < NG; k++) sS[tid][k] *= inv;
    }
    __syncthreads();
#pragma unroll
    for (int i = 0; i < 8; i++) {
        int e = i * 256 + tid, r = e >> 7, c = e & 127;
        float a = 0.f;
#pragma unroll
        for (int k = 0; k < NG; k++) a += sS[r][k] * sVf[k * DM + c];
        sQ[e] = a + st[e];
    }
    __syncthreads();
    int warp = tid >> 5, lane = tid & 31;
#pragma unroll
    for (int i = 0; i < 2; i++) {
        int r = warp * 2 + i;
        float4 v0 = *(const float4*)&sQ[r * DM + lane * 4];
        float s = v0.x + v0.y + v0.z + v0.w;
        float q = v0.x * v0.x + v0.y * v0.y + v0.z * v0.z + v0.w * v0.w;
        s = warp_sum(s); q = warp_sum(q);
        float m = s * (1.f / DM);
        float rs = rsqrtf(q * (1.f / DM) - m * m + LNE);
        float4 o = {(v0.x - m) * rs, (v0.y - m) * rs, (v0.z - m) * rs, (v0.w - m) * rs};
        *(float4*)&out[base + r * DM + lane * 4] = o;
    }
}

extern "C" void kernel_launch(void* const* d_in, const int* in_sizes, int n_in,
                              void* d_out, int out_size) {
    const float* g    = (const float*)d_in[0];
    const float* LF   = (const float*)d_in[1];
    const float* Wvis = (const float*)d_in[2];
    const float* Wtxt = (const float*)d_in[3];
    const float* Wq   = (const float*)d_in[4];
    const float* Wk   = (const float*)d_in[5];
    const float* Wv   = (const float*)d_in[6];
    const float* W1   = (const float*)d_in[7];
    const float* W2   = (const float*)d_in[8];
    const float* Wqf  = (const float*)d_in[9];
    const float* Wkf  = (const float*)d_in[10];
    const float* Wvf  = (const float*)d_in[11];
    float* out = (float*)d_out;

    const int GEMM_SMEM = (64 * 132 + 128 * 132) * 4;          // 101376
    const int VIS_SMEM  = (64 * 68 + 128 * 68) * 4;            // 52224
    cudaFuncSetAttribute(attn_kernel, cudaFuncAttributeMaxDynamicSharedMemorySize, ATTN_SMEM);
    cudaFuncSetAttribute(kv_kernel, cudaFuncAttributeMaxDynamicSharedMemorySize, GEMM_SMEM);
    cudaFuncSetAttribute(qproj_kernel, cudaFuncAttributeMaxDynamicSharedMemorySize, GEMM_SMEM);
    cudaFuncSetAttribute(visual_mma, cudaFuncAttributeMaxDynamicSharedMemorySize, VIS_SMEM);
    cudaFuncSetAttribute(ffn_tf32, cudaFuncAttributeMaxDynamicSharedMemorySize, FFN_SMEM);

    convert_kernel<<<dim3(1024, 12), 256>>>(W1, W2, Wq, Wk, Wv, Wqf, Wvis);   // 0
    text_kernel<<<1, 128>>>(g, Wtxt, Wkf, Wvf, Wq);                           // 1
    visual_mma<<<TFR / 64, 256, VIS_SMEM>>>(LF);                              // 2
    kv_kernel<<<dim3(TFR / 64, 4), 256, GEMM_SMEM>>>();                       // 3
    attn_kernel<<<TFR / 2, 256, ATTN_SMEM>>>(0);                              // 4
    ffn_tf32<<<NTOK / 128, 512, FFN_SMEM>>>(0);                               // 5 <- profiled
    qproj_kernel<<<NTOK / 64, 256, GEMM_SMEM>>>(0);                           // 6
    attn_kernel<<<TFR / 2, 256, ATTN_SMEM>>>(1);                              // 7
    ffn_tf32<<<NTOK / 128, 512, FFN_SMEM>>>(1);                               // 8
    qproj_kernel<<<NTOK / 64, 256, GEMM_SMEM>>>(1);                           // 9
    final_kernel<<<TFR, 256>>>(out);                                          // 10
}

// round 9
// speedup vs baseline: 1.0279x; 1.0153x over previous
#include <cuda_runtime.h>
#include <cuda_bf16.h>
#include <cstdint>

#define TFR 4096
#define DM 128
#define LQ 64
#define NG 16
#define FD 2048
#define GFD 512
#define NTOK (TFR * NG)
#define LNE 1e-5f

// ---------------- device-global scratch ------------------------------------
__device__ float g_t0ln[NG * DM];
__device__ float g_Q0[NG * DM];
__device__ float g_Kf[NG * DM];
__device__ float g_Vf[NG * DM];
__device__ float g_K[2][TFR * DM];
__device__ float g_V[2][TFR * DM];
__device__ float g_t[NTOK * DM];
__device__ float g_Qp[NTOK * DM];

// transposed ([n][k]) weights, tf32 bit patterns
__device__ uint32_t g_W1t[2][FD * DM];   // [2048][128]
__device__ uint32_t g_W2t[2][DM * FD];   // [128][2048]
__device__ uint32_t g_Wqt[2][DM * DM];
__device__ uint32_t g_Wkt[2][DM * DM];
__device__ uint32_t g_Wvt[2][DM * DM];
__device__ uint32_t g_Wqft[DM * DM];
__device__ uint32_t g_Wvist[DM * FD];    // [128][2048]

__device__ __forceinline__ float warp_sum(float v) {
#pragma unroll
    for (int o = 16; o > 0; o >>= 1) v += __shfl_xor_sync(0xffffffffu, v, o);
    return v;
}
__device__ __forceinline__ uint32_t cvta_s(const void* p) {
    return (uint32_t)__cvta_generic_to_shared(p);
}
__device__ __forceinline__ uint32_t f2tf(float v) {
    uint32_t r;
    asm("cvt.rna.tf32.f32 %0, %1;" : "=r"(r) : "f"(v));
    return r;
}
__device__ __forceinline__ void mma_tf32(float c[4], const uint32_t a[4],
                                         uint32_t b0, uint32_t b1) {
    asm volatile(
        "mma.sync.aligned.m16n8k8.row.col.f32.tf32.tf32.f32 "
        "{%0,%1,%2,%3},{%4,%5,%6,%7},{%8,%9},{%0,%1,%2,%3};"
        : "+f"(c[0]), "+f"(c[1]), "+f"(c[2]), "+f"(c[3])
        : "r"(a[0]), "r"(a[1]), "r"(a[2]), "r"(a[3]), "r"(b0), "r"(b1));
}
__device__ __forceinline__ void ldA(uint32_t a[4], const uint32_t* s, int m0,
                                    int k0, int stride, int lane) {
    int r = m0 + (lane >> 2), c = k0 + (lane & 3);
    a[0] = s[r * stride + c];
    a[1] = s[(r + 8) * stride + c];
    a[2] = s[r * stride + c + 4];
    a[3] = s[(r + 8) * stride + c + 4];
}
__device__ __forceinline__ void ldB(uint32_t b[2], const uint32_t* s, int n0,
                                    int k0, int stride, int lane) {
    int n = n0 + (lane >> 2), c = k0 + (lane & 3);
    b[0] = s[n * stride + c];
    b[1] = s[n * stride + c + 4];
}
#define CP16(dst, src) \
    asm volatile("cp.async.cg.shared.global [%0], [%1], 16;" :: "r"(dst), "l"(src))
#define CP_COMMIT() asm volatile("cp.async.commit_group;" ::: "memory")
#define CP_WAIT1() asm volatile("cp.async.wait_group 1;" ::: "memory")

// ---------------- convert + text (one launch) -------------------------------
// grid (1024, 13). y<12: weight convert segs. y==12,x==0: text pipeline.
__global__ void __launch_bounds__(256) convtext_kernel(
    const float* W1, const float* W2, const float* Wq, const float* Wk,
    const float* Wv, const float* Wqf, const float* Wvis,
    const float* g, const float* Wtxt, const float* Wkf, const float* Wvf) {
    __shared__ float sg[NG * GFD];
    __shared__ float sln[NG * DM];
    int seg = blockIdx.y;
    int tid = threadIdx.x;
    if (seg < 12) {
        const float* src;
        uint32_t* dst;
        int K, N;
        switch (seg) {
            case 0:  src = W1;                 dst = g_W1t[0]; K = DM; N = FD; break;
            case 1:  src = W1 + (size_t)DM*FD; dst = g_W1t[1]; K = DM; N = FD; break;
            case 2:  src = W2;                 dst = g_W2t[0]; K = FD; N = DM; break;
            case 3:  src = W2 + (size_t)FD*DM; dst = g_W2t[1]; K = FD; N = DM; break;
            case 4:  src = Wq;                 dst = g_Wqt[0]; K = DM; N = DM; break;
            case 5:  src = Wq + DM*DM;         dst = g_Wqt[1]; K = DM; N = DM; break;
            case 6:  src = Wk;                 dst = g_Wkt[0]; K = DM; N = DM; break;
            case 7:  src = Wk + DM*DM;         dst = g_Wkt[1]; K = DM; N = DM; break;
            case 8:  src = Wv;                 dst = g_Wvt[0]; K = DM; N = DM; break;
            case 9:  src = Wv + DM*DM;         dst = g_Wvt[1]; K = DM; N = DM; break;
            case 10: src = Wqf;                dst = g_Wqft;   K = DM; N = DM; break;
            default: src = Wvis;               dst = g_Wvist;  K = FD; N = DM; break;
        }
        int idx = blockIdx.x * 256 + tid;
        if (idx >= K * N) return;
        int k = idx / N, n = idx - k * N;
        dst[(size_t)n * K + k] = f2tf(src[idx]);
        return;
    }
    // ---- text path (256 threads, block (x==0,y==12)) ----
    if (blockIdx.x != 0) return;
    bool act = tid < 128;
    int c = tid;  // column when act
    for (int i = tid; i < NG * GFD; i += 256) sg[i] = g[i];
    __syncthreads();
    float acc[NG];
#pragma unroll
    for (int r = 0; r < NG; r++) acc[r] = 0.f;
    if (act) {
        for (int k = 0; k < GFD; k++) {
            float w = Wtxt[k * DM + c];
#pragma unroll
            for (int r = 0; r < NG; r++) acc[r] += sg[r * GFD + k] * w;
        }
    }
    __syncthreads();
    float* st = sg;
    if (act) {
#pragma unroll
        for (int r = 0; r < NG; r++) st[r * DM + c] = acc[r];
    }
    __syncthreads();
    if (act) {
        float a1[NG], a2[NG];
#pragma unroll
        for (int r = 0; r < NG; r++) { a1[r] = 0.f; a2[r] = 0.f; }
        for (int k = 0; k < DM; k++) {
            float w1 = Wkf[k * DM + c];
            float w2 = Wvf[k * DM + c];
#pragma unroll
            for (int r = 0; r < NG; r++) {
                float tv = st[r * DM + k];
                a1[r] += tv * w1;
                a2[r] += tv * w2;
            }
        }
#pragma unroll
        for (int r = 0; r < NG; r++) {
            g_Kf[r * DM + c] = a1[r];
            g_Vf[r * DM + c] = a2[r];
        }
    }
    int warp = tid >> 5, lane = tid & 31;
    if (warp < 4) {
#pragma unroll
        for (int i = 0; i < 4; i++) {
            int r = warp * 4 + i;
            float4 v = *(const float4*)&st[r * DM + lane * 4];
            float s = v.x + v.y + v.z + v.w;
            float q = v.x * v.x + v.y * v.y + v.z * v.z + v.w * v.w;
            s = warp_sum(s); q = warp_sum(q);
            float m = s * (1.f / DM);
            float rs = rsqrtf(q * (1.f / DM) - m * m + LNE);
            float4 o = {(v.x - m) * rs, (v.y - m) * rs, (v.z - m) * rs, (v.w - m) * rs};
            *(float4*)&sln[r * DM + lane * 4] = o;
            *(float4*)&g_t0ln[r * DM + lane * 4] = o;
        }
    }
    __syncthreads();
    if (act) {
        float aq[NG];
#pragma unroll
        for (int r = 0; r < NG; r++) aq[r] = 0.f;
        for (int k = 0; k < DM; k++) {
            float w = Wq[k * DM + c];   // layer-0 Wq
#pragma unroll
            for (int r = 0; r < NG; r++) aq[r] += sln[r * DM + k] * w;
        }
#pragma unroll
        for (int r = 0; r < NG; r++) g_Q0[r * DM + c] = aq[r];
    }
}

// ---------------- fused visual + K/V projections ---------------------------
// grid 64, 256 thr. Phase1: lnvis tile (tf32 in sX). Phase2: 4 projections.
// smem u32: sX [64][132]=8448 | phase1 sA[64][68]@8448 sB[128][68]@12800
//           phase2 sBw[128][132]@8448 ; total 25344 u32
#define VISKV_SMEM (25344 * 4)
__global__ void __launch_bounds__(256) viskv_kernel(const float* __restrict__ LF) {
    extern __shared__ uint32_t smv[];
    uint32_t* sX = smv;                 // [64][132] tf32 (also float staging)
    uint32_t* sA = smv + 8448;          // [64][68]
    uint32_t* sB = smv + 12800;         // [128][68]
    int tid = threadIdx.x, lane = tid & 31, warp = tid >> 5;
    size_t row0 = (size_t)blockIdx.x * 64;
    int m0 = (warp >> 1) * 16, n0 = (warp & 1) * 64;
    float acc[8][4];
#pragma unroll
    for (int t = 0; t < 8; t++)
#pragma unroll
        for (int j = 0; j < 4; j++) acc[t][j] = 0.f;

    for (int kc = 0; kc < FD; kc += 64) {
#pragma unroll
        for (int u = 0; u < 4; u++) {
            int e = u * 256 + tid;
            int r = e >> 4, c4 = (e & 15) * 4;
            float4 v = *(const float4*)&LF[(row0 + r) * FD + kc + c4];
            uint4 t;
            t.x = f2tf(v.x); t.y = f2tf(v.y); t.z = f2tf(v.z); t.w = f2tf(v.w);
            *(uint4*)&sA[r * 68 + c4] = t;
        }
#pragma unroll
        for (int u = 0; u < 8; u++) {
            int e = u * 256 + tid;
            int n = e >> 4, kk = (e & 15) * 4;
            *(uint4*)&sB[n * 68 + kk] = *(const uint4*)&g_Wvist[(size_t)n * FD + kc + kk];
        }
        __syncthreads();
#pragma unroll
        for (int ks = 0; ks < 8; ks++) {
            int k0 = ks * 8;
            uint32_t a[4];
            ldA(a, sA, m0, k0, 68, lane);
#pragma unroll
            for (int nt = 0; nt < 8; nt++) {
                uint32_t b[2];
                ldB(b, sB, n0 + nt * 8, k0, 68, lane);
                mma_tf32(acc[nt], a, b[0], b[1]);
            }
        }
        __syncthreads();
    }
    // stage acc -> sX (as float), then in-place LN -> tf32
    float* sXf = (float*)sX;
    int r = m0 + (lane >> 2), cb = (lane & 3) * 2;
#pragma unroll
    for (int t = 0; t < 8; t++) {
        int col = n0 + t * 8 + cb;
        sXf[r * 132 + col] = acc[t][0];
        sXf[r * 132 + col + 1] = acc[t][1];
        sXf[(r + 8) * 132 + col] = acc[t][2];
        sXf[(r + 8) * 132 + col + 1] = acc[t][3];
    }
    __syncthreads();
#pragma unroll
    for (int i = 0; i < 8; i++) {
        int rr = warp * 8 + i;
        float4 v = *(const float4*)&sXf[rr * 132 + lane * 4];
        float s = v.x + v.y + v.z + v.w;
        float q = v.x * v.x + v.y * v.y + v.z * v.z + v.w * v.w;
        s = warp_sum(s); q = warp_sum(q);
        float m = s * (1.f / DM);
        float rs = rsqrtf(q * (1.f / DM) - m * m + LNE);
        uint4 o;
        o.x = f2tf((v.x - m) * rs); o.y = f2tf((v.y - m) * rs);
        o.z = f2tf((v.z - m) * rs); o.w = f2tf((v.w - m) * rs);
        __syncwarp();
        *(uint4*)&sX[rr * 132 + lane * 4] = o;
    }
    __syncthreads();

    // phase 2: 4 projections using sX
    uint32_t* sBw = smv + 8448;  // [128][132]
#pragma unroll 1
    for (int w = 0; w < 4; w++) {
        const uint32_t* Bt = (w == 0) ? g_Wkt[0] : (w == 1) ? g_Wvt[0]
                           : (w == 2) ? g_Wkt[1] : g_Wvt[1];
        float* C = (w == 0) ? g_K[0] : (w == 1) ? g_V[0]
                 : (w == 2) ? g_K[1] : g_V[1];
#pragma unroll
        for (int u = 0; u < 16; u++) {
            int e = u * 256 + tid;
            int n = e >> 5, kk = (e & 31) * 4;
            *(uint4*)&sBw[n * 132 + kk] = *(const uint4*)&Bt[n * DM + kk];
        }
        __syncthreads();
        float ac[8][4];
#pragma unroll
        for (int t = 0; t < 8; t++)
#pragma unroll
            for (int j = 0; j < 4; j++) ac[t][j] = 0.f;
#pragma unroll
        for (int ks = 0; ks < 16; ks++) {
            int k0 = ks * 8;
            uint32_t a[4];
            ldA(a, sX, m0, k0, 132, lane);
#pragma unroll
            for (int nt = 0; nt < 8; nt++) {
                uint32_t b[2];
                ldB(b, sBw, n0 + nt * 8, k0, 132, lane);
                mma_tf32(ac[nt], a, b[0], b[1]);
            }
        }
#pragma unroll
        for (int t = 0; t < 8; t++) {
            int col = n0 + t * 8 + cb;
            *(float2*)&C[(row0 + r) * DM + col] = make_float2(ac[t][0], ac[t][1]);
            *(float2*)&C[(row0 + r + 8) * DM + col] = make_float2(ac[t][2], ac[t][3]);
        }
        __syncthreads();
    }
}

// ---------------- FFN (+ fused Q projection): tf32, 512 thr ----------------
// smem u32: sX[128][132]=16896 | W1 2x[32][132] @16896 | W2 2x[128][36] @25344
//           H[128][36] @34560  -> 39168 u32 = 156672 B
// epilogue reuses @16896 as sY [128][132] float, then as Wq tile [128][132].
#define FFN_SMEM (39168 * 4)
#define NCH 64

__global__ void __launch_bounds__(512) ffn_tf32(int l) {
    extern __shared__ uint32_t smf[];
    uint32_t* sX = smf;               // [128][132]
    uint32_t* sH = smf + 34560;       // [128][36]
    const uint32_t* W1 = g_W1t[l];
    const uint32_t* W2 = g_W2t[l];
    int tid = threadIdx.x, lane = tid & 31, warp = tid >> 5;
    int wm = warp >> 1, wn = warp & 1;
    int m0 = wm * 16;
    size_t row0 = (size_t)blockIdx.x * 128;
    uint32_t sb = cvta_s(smf);

    // prologue: LN + tf32 X  (16 warps x 8 rows)
#pragma unroll
    for (int i = 0; i < 8; i++) {
        int r = warp * 8 + i;
        float4 v = *(const float4*)&g_t[(row0 + r) * DM + lane * 4];
        float s = v.x + v.y + v.z + v.w;
        float q = v.x * v.x + v.y * v.y + v.z * v.z + v.w * v.w;
        s = warp_sum(s); q = warp_sum(q);
        float m = s * (1.f / DM);
        float rs = rsqrtf(q * (1.f / DM) - m * m + LNE);
        uint4 t;
        t.x = f2tf((v.x - m) * rs); t.y = f2tf((v.y - m) * rs);
        t.z = f2tf((v.z - m) * rs); t.w = f2tf((v.w - m) * rs);
        *(uint4*)&sX[r * 132 + lane * 4] = t;
    }
    // preload chunk 0 into buf 0
    {
        uint32_t w1d = sb + 16896 * 4, w2d = sb + 25344 * 4;
#pragma unroll
        for (int u = 0; u < 2; u++) {
            int e = u * 512 + tid;
            int n = e >> 5, kk = (e & 31) * 4;
            CP16(w1d + (n * 132 + kk) * 4, W1 + (size_t)n * DM + kk);
        }
#pragma unroll
        for (int u = 0; u < 2; u++) {
            int e = u * 512 + tid;
            int n = e >> 3, kk = (e & 7) * 4;
            CP16(w2d + (n * 36 + kk) * 4, W2 + (size_t)n * FD + kk);
        }
        CP_COMMIT();
    }

    float acc2[8][4];
#pragma unroll
    for (int t = 0; t < 8; t++)
#pragma unroll
        for (int j = 0; j < 4; j++) acc2[t][j] = 0.f;

    int lr = lane >> 2, lc = 2 * (lane & 3);
    for (int i = 0; i < NCH; i++) {
        int buf = i & 1, nb = buf ^ 1;
        __syncthreads();
        if (i + 1 < NCH) {
            uint32_t w1d = sb + (16896 + nb * 4224) * 4;
            uint32_t w2d = sb + (25344 + nb * 4608) * 4;
            const uint32_t* W1s = W1 + (size_t)(i + 1) * 32 * DM;
#pragma unroll
            for (int u = 0; u < 2; u++) {
                int e = u * 512 + tid;
                int n = e >> 5, kk = (e & 31) * 4;
                CP16(w1d + (n * 132 + kk) * 4, W1s + (size_t)n * DM + kk);
            }
#pragma unroll
            for (int u = 0; u < 2; u++) {
                int e = u * 512 + tid;
                int n = e >> 3, kk = (e & 7) * 4;
                CP16(w2d + (n * 36 + kk) * 4, W2 + (size_t)n * FD + (i + 1) * 32 + kk);
            }
        }
        CP_COMMIT();
        CP_WAIT1();
        __syncthreads();
        const uint32_t* w1 = smf + 16896 + buf * 4224;
        const uint32_t* w2 = smf + 25344 + buf * 4608;

        float acc1[2][4];
#pragma unroll
        for (int t = 0; t < 2; t++)
#pragma unroll
            for (int j = 0; j < 4; j++) acc1[t][j] = 0.f;
#pragma unroll
        for (int ks = 0; ks < 16; ks++) {
            int k0 = ks * 8;
            uint32_t a[4];
            ldA(a, sX, m0, k0, 132, lane);
#pragma unroll
            for (int nt = 0; nt < 2; nt++) {
                uint32_t b[2];
                ldB(b, w1, wn * 16 + nt * 8, k0, 132, lane);
                mma_tf32(acc1[nt], a, b[0], b[1]);
            }
        }
#pragma unroll
        for (int nt = 0; nt < 2; nt++) {
            int c0 = wn * 16 + nt * 8 + lc;
            sH[(m0 + lr) * 36 + c0] = f2tf(fmaxf(acc1[nt][0], 0.f));
            sH[(m0 + lr) * 36 + c0 + 1] = f2tf(fmaxf(acc1[nt][1], 0.f));
            sH[(m0 + lr + 8) * 36 + c0] = f2tf(fmaxf(acc1[nt][2], 0.f));
            sH[(m0 + lr + 8) * 36 + c0 + 1] = f2tf(fmaxf(acc1[nt][3], 0.f));
        }
        __syncthreads();
#pragma unroll
        for (int ks = 0; ks < 4; ks++) {
            int k0 = ks * 8;
            uint32_t a[4];
            ldA(a, sH, m0, k0, 36, lane);
#pragma unroll
            for (int nt = 0; nt < 8; nt++) {
                uint32_t b[2];
                ldB(b, w2, wn * 64 + nt * 8, k0, 36, lane);
                mma_tf32(acc2[nt], a, b[0], b[1]);
            }
        }
    }
    __syncthreads();

    // epilogue A: y + residual -> sY
    float* sY = (float*)(smf + 16896);
#pragma unroll
    for (int nt = 0; nt < 8; nt++) {
        int col = wn * 64 + nt * 8 + lc;
        int r0 = m0 + lr, r1 = m0 + lr + 8;
        float2 x0 = *(const float2*)&g_t[(row0 + r0) * DM + col];
        float2 x1 = *(const float2*)&g_t[(row0 + r1) * DM + col];
        sY[r0 * 132 + col] = acc2[nt][0] + x0.x;
        sY[r0 * 132 + col + 1] = acc2[nt][1] + x0.y;
        sY[r1 * 132 + col] = acc2[nt][2] + x1.x;
        sY[r1 * 132 + col + 1] = acc2[nt][3] + x1.y;
    }
    __syncthreads();
    // epilogue B: LN (and for l==0 a second exact LN-rescale) -> g_t + sX(tf32)
#pragma unroll
    for (int i = 0; i < 8; i++) {
        int r = warp * 8 + i;
        float4 v = *(const float4*)&sY[r * 132 + lane * 4];
        float s = v.x + v.y + v.z + v.w;
        float q = v.x * v.x + v.y * v.y + v.z * v.z + v.w * v.w;
        s = warp_sum(s); q = warp_sum(q);
        float m = s * (1.f / DM);
        float var = q * (1.f / DM) - m * m;
        float rs = rsqrtf(var + LNE);
        float sc2 = 1.f;
        if (l == 0) {
            float q2 = var / (var + LNE);     // variance of LN output
            sc2 = rsqrtf(q2 + LNE);           // second LN = pure rescale
        }
        float f = rs * sc2;
        float4 o = {(v.x - m) * f, (v.y - m) * f, (v.z - m) * f, (v.w - m) * f};
        __syncwarp();
        *(float4*)&g_t[(row0 + r) * DM + lane * 4] = o;
        uint4 tt;
        tt.x = f2tf(o.x); tt.y = f2tf(o.y); tt.z = f2tf(o.z); tt.w = f2tf(o.w);
        *(uint4*)&sX[r * 132 + lane * 4] = tt;
    }
    __syncthreads();
    // epilogue C: fused Q projection  g_Qp = out @ Wq
    {
        const uint32_t* Wq = (l == 0) ? g_Wqt[1] : g_Wqft;
        uint32_t* sBW = smf + 16896;  // [128][132] overwrites sY
#pragma unroll
        for (int u = 0; u < 8; u++) {
            int e = u * 512 + tid;
            int n = e >> 5, kk = (e & 31) * 4;
            *(uint4*)&sBW[n * 132 + kk] = *(const uint4*)&Wq[n * DM + kk];
        }
        __syncthreads();
        float aq[8][4];
#pragma unroll
        for (int t = 0; t < 8; t++)
#pragma unroll
            for (int j = 0; j < 4; j++) aq[t][j] = 0.f;
#pragma unroll
        for (int ks = 0; ks < 16; ks++) {
            int k0 = ks * 8;
            uint32_t a[4];
            ldA(a, sX, m0, k0, 132, lane);
#pragma unroll
            for (int nt = 0; nt < 8; nt++) {
                uint32_t b[2];
                ldB(b, sBW, wn * 64 + nt * 8, k0, 132, lane);
                mma_tf32(aq[nt], a, b[0], b[1]);
            }
        }
        int r0 = m0 + lr;
#pragma unroll
        for (int nt = 0; nt < 8; nt++) {
            int col = wn * 64 + nt * 8 + lc;
            *(float2*)&g_Qp[(row0 + r0) * DM + col] = make_float2(aq[nt][0], aq[nt][1]);
            *(float2*)&g_Qp[(row0 + r0 + 8) * DM + col] = make_float2(aq[nt][2], aq[nt][3]);
        }
    }
}

// ---------------- sliding-window cross attention: 2 frames / block ---------
#define ATTN_SMEM ((4096 + 4096 + 2 * 65 * 128) * 4)

__global__ void __launch_bounds__(256, 2) attn_kernel(int l) {
    extern __shared__ float sm[];
    float* sK = sm + 8192;
    float* sV = sK + 65 * 128;
    const float* Kl = g_K[l];
    const float* Vl = g_V[l];
    int tid = threadIdx.x;
    int grp = tid >> 7, gt = tid & 127;
    int f0 = blockIdx.x * 2;
    int f = f0 + grp;
    size_t base = (size_t)f * NG * DM;
    float* mQ = sm + grp * 2048;
    float* mR = sm + 4096 + grp * 2048;
    int gw = gt >> 5, lane = gt & 31;

    if (l == 0) {
#pragma unroll
        for (int i = 0; i < 16; i++) {
            int e = i * 128 + gt;
            mQ[e] = g_Q0[e];
            mR[e] = g_t0ln[e];
        }
    } else {
        // g_t already holds tq (ffn epilogue applied the second LN)
#pragma unroll
        for (int i = 0; i < 16; i++) {
            int e = i * 128 + gt;
            mQ[e] = g_Qp[base + e];
            mR[e] = g_t[base + e];
        }
    }
    for (int idx = tid; idx < 65 * 128; idx += 256) {
        int w = idx >> 7;
        int src = f0 - (LQ - 1) + w;
        float kv = 0.f, vv = 0.f;
        if (src >= 0) {
            kv = Kl[(size_t)src * DM + (idx & 127)];
            vv = Vl[(size_t)src * DM + (idx & 127)];
        }
        sK[idx] = kv;
        sV[idx] = vv;
    }
    __syncthreads();
    int h = gt >> 4, q = gt & 15;
    float4 qv[4];
#pragma unroll
    for (int d = 0; d < 4; d++) qv[d] = *(const float4*)&mQ[q * DM + h * 16 + d * 4];
    float sc[LQ];
    float mx = -1e30f;
#pragma unroll
    for (int k = 0; k < LQ; k++) {
        const float4* kr = (const float4*)&sK[(k + grp) * DM + h * 16];
        float s = 0.f;
#pragma unroll
        for (int d = 0; d < 4; d++) {
            float4 kk = kr[d];
            s += qv[d].x * kk.x + qv[d].y * kk.y + qv[d].z * kk.z + qv[d].w * kk.w;
        }
        s *= 0.25f;
        sc[k] = s;
        mx = fmaxf(mx, s);
    }
    float sum = 0.f;
#pragma unroll
    for (int k = 0; k < LQ; k++) {
        float e = __expf(sc[k] - mx);
        sc[k] = e;
        sum += e;
    }
    float inv = 1.f / sum;
    float4 ctx[4];
#pragma unroll
    for (int d = 0; d < 4; d++) ctx[d] = make_float4(0.f, 0.f, 0.f, 0.f);
#pragma unroll
    for (int k = 0; k < LQ; k++) {
        float p = sc[k];
        const float4* vr = (const float4*)&sV[(k + grp) * DM + h * 16];
#pragma unroll
        for (int d = 0; d < 4; d++) {
            float4 vv = vr[d];
            ctx[d].x += p * vv.x; ctx[d].y += p * vv.y;
            ctx[d].z += p * vv.z; ctx[d].w += p * vv.w;
        }
    }
    __syncthreads();
#pragma unroll
    for (int d = 0; d < 4; d++) {
        float4 o = {ctx[d].x * inv, ctx[d].y * inv, ctx[d].z * inv, ctx[d].w * inv};
        *(float4*)&mQ[q * DM + h * 16 + d * 4] = o;
    }
    __syncthreads();
#pragma unroll
    for (int i = 0; i < 4; i++) {
        int r = gw * 4 + i;
        float vals[4];
        float s = 0.f, qq = 0.f;
#pragma unroll
        for (int j = 0; j < 4; j++) {
            int cc = lane + 32 * j;
            float v = mQ[r * DM + cc] + mR[r * DM + cc];
            vals[j] = v;
            s += v;
            qq += v * v;
        }
        s = warp_sum(s); qq = warp_sum(qq);
        float m = s * (1.f / DM);
        float rs = rsqrtf(qq * (1.f / DM) - m * m + LNE);
#pragma unroll
        for (int j = 0; j < 4; j++)
            g_t[base + r * DM + lane + 32 * j] = (vals[j] - m) * rs;
    }
}

// ---------------- final single-head attention ------------------------------
__global__ void final_kernel(float* __restrict__ out) {
    __shared__ float st[NG * DM];
    __shared__ float sQ[NG * DM];
    __shared__ float sKf[NG * 132];
    __shared__ float sVf[NG * DM];
    __shared__ float sS[NG][NG + 1];
    int tid = threadIdx.x;
    int f = blockIdx.x;
    size_t base = (size_t)f * NG * DM;
#pragma unroll
    for (int i = 0; i < 8; i++) {
        int e = i * 256 + tid, r = e >> 7, c = e & 127;
        st[e] = g_t[base + e];
        sQ[e] = g_Qp[base + e];
        sKf[r * 132 + c] = g_Kf[e];
        sVf[e] = g_Vf[e];
    }
    __syncthreads();
    {
        int qr = tid >> 4, kr = tid & 15;
        float a = 0.f;
        for (int k = 0; k < DM; k++) a += sQ[qr * DM + k] * sKf[kr * 132 + k];
        sS[qr][kr] = a * 0.08838834764831843f;
    }
    __syncthreads();
    if (tid < NG) {
        float mx = -1e30f;
#pragma unroll
        for (int k = 0; k < NG; k++) mx = fmaxf(mx, sS[tid][k]);
        float sum = 0.f;
#pragma unroll
        for (int k = 0; k < NG; k++) {
            float e = __expf(sS[tid][k] - mx);
            sS[tid][k] = e;
            sum += e;
        }
        float inv = 1.f / sum;
#pragma unroll
        for (int k = 0; k < NG; k++) sS[tid][k] *= inv;
    }
    __syncthreads();
#pragma unroll
    for (int i = 0; i < 8; i++) {
        int e = i * 256 + tid, r = e >> 7, c = e & 127;
        float a = 0.f;
#pragma unroll
        for (int k = 0; k < NG; k++) a += sS[r][k] * sVf[k * DM + c];
        sQ[e] = a + st[e];
    }
    __syncthreads();
    int warp = tid >> 5, lane = tid & 31;
#pragma unroll
    for (int i = 0; i < 2; i++) {
        int r = warp * 2 + i;
        float4 v0 = *(const float4*)&sQ[r * DM + lane * 4];
        float s = v0.x + v0.y + v0.z + v0.w;
        float q = v0.x * v0.x + v0.y * v0.y + v0.z * v0.z + v0.w * v0.w;
        s = warp_sum(s); q = warp_sum(q);
        float m = s * (1.f / DM);
        float rs = rsqrtf(q * (1.f / DM) - m * m + LNE);
        float4 o = {(v0.x - m) * rs, (v0.y - m) * rs, (v0.z - m) * rs, (v0.w - m) * rs};
        *(float4*)&out[base + r * DM + lane * 4] = o;
    }
}

extern "C" void kernel_launch(void* const* d_in, const int* in_sizes, int n_in,
                              void* d_out, int out_size) {
    const float* g    = (const float*)d_in[0];
    const float* LF   = (const float*)d_in[1];
    const float* Wvis = (const float*)d_in[2];
    const float* Wtxt = (const float*)d_in[3];
    const float* Wq   = (const float*)d_in[4];
    const float* Wk   = (const float*)d_in[5];
    const float* Wv   = (const float*)d_in[6];
    const float* W1   = (const float*)d_in[7];
    const float* W2   = (const float*)d_in[8];
    const float* Wqf  = (const float*)d_in[9];
    const float* Wkf  = (const float*)d_in[10];
    const float* Wvf  = (const float*)d_in[11];
    float* out = (float*)d_out;

    cudaFuncSetAttribute(attn_kernel, cudaFuncAttributeMaxDynamicSharedMemorySize, ATTN_SMEM);
    cudaFuncSetAttribute(viskv_kernel, cudaFuncAttributeMaxDynamicSharedMemorySize, VISKV_SMEM);
    cudaFuncSetAttribute(ffn_tf32, cudaFuncAttributeMaxDynamicSharedMemorySize, FFN_SMEM);

    convtext_kernel<<<dim3(1024, 13), 256>>>(W1, W2, Wq, Wk, Wv, Wqf, Wvis,
                                             g, Wtxt, Wkf, Wvf);              // 0
    viskv_kernel<<<TFR / 64, 256, VISKV_SMEM>>>(LF);                          // 1
    attn_kernel<<<TFR / 2, 256, ATTN_SMEM>>>(0);                              // 2
    ffn_tf32<<<NTOK / 128, 512, FFN_SMEM>>>(0);                               // 3 <- target profile slot
    attn_kernel<<<TFR / 2, 256, ATTN_SMEM>>>(1);                              // 4
    ffn_tf32<<<NTOK / 128, 512, FFN_SMEM>>>(1);                               // 5
    final_kernel<<<TFR, 256>>>(out);                                          // 6
}

// round 10
// speedup vs baseline: 1.2658x; 1.2314x over previous
#include <cuda_runtime.h>
#include <cuda_bf16.h>
#include <cstdint>

#define TFR 4096
#define DM 128
#define LQ 64
#define NG 16
#define FD 2048
#define GFD 512
#define NTOK (TFR * NG)
#define LNE 1e-5f

// ---------------- device-global scratch ------------------------------------
__device__ float g_t0ln[NG * DM];
__device__ float g_Q0[NG * DM];
__device__ float g_Kf[NG * DM];
__device__ float g_Vf[NG * DM];
__device__ float g_K[2][TFR * DM];
__device__ float g_V[2][TFR * DM];
__device__ float g_t[NTOK * DM];
__device__ float g_Qp[NTOK * DM];

// weights (tf32 bits). W1/W2/Wq1/Wqf in FRAGMENT order; others [n][k].
__device__ uint32_t g_W1t[2][FD * DM];
__device__ uint32_t g_W2t[2][DM * FD];
__device__ uint32_t g_Wq1f[DM * DM];
__device__ uint32_t g_Wqff[DM * DM];
__device__ uint32_t g_Wkt[2][DM * DM];
__device__ uint32_t g_Wvt[2][DM * DM];
__device__ uint32_t g_Wvist[DM * FD];

__device__ __forceinline__ float warp_sum(float v) {
#pragma unroll
    for (int o = 16; o > 0; o >>= 1) v += __shfl_xor_sync(0xffffffffu, v, o);
    return v;
}
__device__ __forceinline__ uint32_t cvta_s(const void* p) {
    return (uint32_t)__cvta_generic_to_shared(p);
}
__device__ __forceinline__ uint32_t f2tf(float v) {
    uint32_t r;
    asm("cvt.rna.tf32.f32 %0, %1;" : "=r"(r) : "f"(v));
    return r;
}
__device__ __forceinline__ void mma_tf32(float c[4], const uint32_t a[4],
                                         uint32_t b0, uint32_t b1) {
    asm volatile(
        "mma.sync.aligned.m16n8k8.row.col.f32.tf32.tf32.f32 "
        "{%0,%1,%2,%3},{%4,%5,%6,%7},{%8,%9},{%0,%1,%2,%3};"
        : "+f"(c[0]), "+f"(c[1]), "+f"(c[2]), "+f"(c[3])
        : "r"(a[0]), "r"(a[1]), "r"(a[2]), "r"(a[3]), "r"(b0), "r"(b1));
}
__device__ __forceinline__ void ldA(uint32_t a[4], const uint32_t* s, int m0,
                                    int k0, int stride, int lane) {
    int r = m0 + (lane >> 2), c = k0 + (lane & 3);
    a[0] = s[r * stride + c];
    a[1] = s[(r + 8) * stride + c];
    a[2] = s[r * stride + c + 4];
    a[3] = s[(r + 8) * stride + c + 4];
}
__device__ __forceinline__ void ldB(uint32_t b[2], const uint32_t* s, int n0,
                                    int k0, int stride, int lane) {
    int n = n0 + (lane >> 2), c = k0 + (lane & 3);
    b[0] = s[n * stride + c];
    b[1] = s[n * stride + c + 4];
}
#define CP16(dst, src) \
    asm volatile("cp.async.cg.shared.global [%0], [%1], 16;" :: "r"(dst), "l"(src))
#define CP_COMMIT() asm volatile("cp.async.commit_group;" ::: "memory")
#define CP_WAIT1() asm volatile("cp.async.wait_group 1;" ::: "memory")

// ---------------- convert (frag layouts) + text ------------------------------
// grid (1024, 12): y 0,1 W1frag | 2,3 W2frag | 4 Wq1frag | 5 Wqffrag |
//                  6,7 Wk [n][k] | 8,9 Wv | 10 Wvis | 11,x==0: text
__global__ void __launch_bounds__(256) convtext_kernel(
    const float* W1, const float* W2, const float* Wq, const float* Wk,
    const float* Wv, const float* Wqf, const float* Wvis,
    const float* g, const float* Wtxt, const float* Wkf, const float* Wvf) {
    __shared__ float sg[NG * GFD];
    __shared__ float sln[NG * DM];
    int seg = blockIdx.y;
    int tid = threadIdx.x;
    int idx = blockIdx.x * 256 + tid;
    if (seg <= 1) {  // W1[l]: src [128k][2048n] -> frag chunks of 32n
        if (idx >= DM * FD) return;
        const float* src = W1 + (size_t)seg * DM * FD;
        uint32_t* dst = g_W1t[seg];
        int k = idx >> 11, n = idx & 2047;
        int chunk = n >> 5, nn = n & 31;
        int t = nn >> 3, lane = (nn & 7) * 4 + (k & 3);
        int ks = k >> 3, p = ks >> 1, word = (ks & 1) * 2 + ((k >> 2) & 1);
        dst[chunk * 4096 + (t * 8 + p) * 128 + lane * 4 + word] = f2tf(src[idx]);
        return;
    }
    if (seg <= 3) {  // W2[l]: src [2048k][128n] -> frag chunks of 32k
        if (idx >= FD * DM) return;
        const float* src = W2 + (size_t)(seg - 2) * FD * DM;
        uint32_t* dst = g_W2t[seg - 2];
        int k = idx >> 7, n = idx & 127;
        int chunk = k >> 5, kk = k & 31;
        int ks = kk >> 3, p = ks >> 1, word = (ks & 1) * 2 + ((kk >> 2) & 1);
        int t = n >> 3, lane = (n & 7) * 4 + (kk & 3);
        dst[chunk * 4096 + (t * 2 + p) * 128 + lane * 4 + word] = f2tf(src[idx]);
        return;
    }
    if (seg <= 5) {  // Wq[1] / Wqf: src [128k][128n] -> frag (16t x 8p)
        if (idx >= DM * DM) return;
        const float* src = (seg == 4) ? (Wq + DM * DM) : Wqf;
        uint32_t* dst = (seg == 4) ? g_Wq1f : g_Wqff;
        int k = idx >> 7, n = idx & 127;
        int t = n >> 3, lane = (n & 7) * 4 + (k & 3);
        int ks = k >> 3, p = ks >> 1, word = (ks & 1) * 2 + ((k >> 2) & 1);
        dst[(t * 8 + p) * 128 + lane * 4 + word] = f2tf(src[idx]);
        return;
    }
    if (seg <= 10) {  // [n][k] transpose convert
        const float* src;
        uint32_t* dst;
        int K, N;
        switch (seg) {
            case 6:  src = Wk;          dst = g_Wkt[0]; K = DM; N = DM; break;
            case 7:  src = Wk + DM*DM;  dst = g_Wkt[1]; K = DM; N = DM; break;
            case 8:  src = Wv;          dst = g_Wvt[0]; K = DM; N = DM; break;
            case 9:  src = Wv + DM*DM;  dst = g_Wvt[1]; K = DM; N = DM; break;
            default: src = Wvis;        dst = g_Wvist;  K = FD; N = DM; break;
        }
        if (idx >= K * N) return;
        int k = idx / N, n = idx - k * N;
        dst[(size_t)n * K + k] = f2tf(src[idx]);
        return;
    }
    // ---- text path (block (0,11)) ----
    if (blockIdx.x != 0) return;
    bool act = tid < 128;
    int c = tid;
    for (int i = tid; i < NG * GFD; i += 256) sg[i] = g[i];
    __syncthreads();
    float acc[NG];
#pragma unroll
    for (int r = 0; r < NG; r++) acc[r] = 0.f;
    if (act) {
        for (int k = 0; k < GFD; k++) {
            float w = Wtxt[k * DM + c];
#pragma unroll
            for (int r = 0; r < NG; r++) acc[r] += sg[r * GFD + k] * w;
        }
    }
    __syncthreads();
    float* st = sg;
    if (act) {
#pragma unroll
        for (int r = 0; r < NG; r++) st[r * DM + c] = acc[r];
    }
    __syncthreads();
    if (act) {
        float a1[NG], a2[NG];
#pragma unroll
        for (int r = 0; r < NG; r++) { a1[r] = 0.f; a2[r] = 0.f; }
        for (int k = 0; k < DM; k++) {
            float w1 = Wkf[k * DM + c];
            float w2 = Wvf[k * DM + c];
#pragma unroll
            for (int r = 0; r < NG; r++) {
                float tv = st[r * DM + k];
                a1[r] += tv * w1;
                a2[r] += tv * w2;
            }
        }
#pragma unroll
        for (int r = 0; r < NG; r++) {
            g_Kf[r * DM + c] = a1[r];
            g_Vf[r * DM + c] = a2[r];
        }
    }
    int warp = tid >> 5, lane = tid & 31;
    if (warp < 4) {
#pragma unroll
        for (int i = 0; i < 4; i++) {
            int r = warp * 4 + i;
            float4 v = *(const float4*)&st[r * DM + lane * 4];
            float s = v.x + v.y + v.z + v.w;
            float q = v.x * v.x + v.y * v.y + v.z * v.z + v.w * v.w;
            s = warp_sum(s); q = warp_sum(q);
            float m = s * (1.f / DM);
            float rs = rsqrtf(q * (1.f / DM) - m * m + LNE);
            float4 o = {(v.x - m) * rs, (v.y - m) * rs, (v.z - m) * rs, (v.w - m) * rs};
            *(float4*)&sln[r * DM + lane * 4] = o;
            *(float4*)&g_t0ln[r * DM + lane * 4] = o;
        }
    }
    __syncthreads();
    if (act) {
        float aq[NG];
#pragma unroll
        for (int r = 0; r < NG; r++) aq[r] = 0.f;
        for (int k = 0; k < DM; k++) {
            float w = Wq[k * DM + c];
#pragma unroll
            for (int r = 0; r < NG; r++) aq[r] += sln[r * DM + k] * w;
        }
#pragma unroll
        for (int r = 0; r < NG; r++) g_Q0[r * DM + c] = aq[r];
    }
}

// ---------------- fused visual + K/V projections ---------------------------
#define VISKV_SMEM (25344 * 4)
__global__ void __launch_bounds__(256) viskv_kernel(const float* __restrict__ LF) {
    extern __shared__ uint32_t smv[];
    uint32_t* sX = smv;                 // [64][132]
    uint32_t* sA = smv + 8448;          // [64][68]
    uint32_t* sB = smv + 12800;         // [128][68]
    int tid = threadIdx.x, lane = tid & 31, warp = tid >> 5;
    size_t row0 = (size_t)blockIdx.x * 64;
    int m0 = (warp >> 1) * 16, n0 = (warp & 1) * 64;
    float acc[8][4];
#pragma unroll
    for (int t = 0; t < 8; t++)
#pragma unroll
        for (int j = 0; j < 4; j++) acc[t][j] = 0.f;

    for (int kc = 0; kc < FD; kc += 64) {
#pragma unroll
        for (int u = 0; u < 4; u++) {
            int e = u * 256 + tid;
            int r = e >> 4, c4 = (e & 15) * 4;
            float4 v = *(const float4*)&LF[(row0 + r) * FD + kc + c4];
            uint4 t;
            t.x = f2tf(v.x); t.y = f2tf(v.y); t.z = f2tf(v.z); t.w = f2tf(v.w);
            *(uint4*)&sA[r * 68 + c4] = t;
        }
#pragma unroll
        for (int u = 0; u < 8; u++) {
            int e = u * 256 + tid;
            int n = e >> 4, kk = (e & 15) * 4;
            *(uint4*)&sB[n * 68 + kk] = *(const uint4*)&g_Wvist[(size_t)n * FD + kc + kk];
        }
        __syncthreads();
#pragma unroll
        for (int ks = 0; ks < 8; ks++) {
            int k0 = ks * 8;
            uint32_t a[4];
            ldA(a, sA, m0, k0, 68, lane);
#pragma unroll
            for (int nt = 0; nt < 8; nt++) {
                uint32_t b[2];
                ldB(b, sB, n0 + nt * 8, k0, 68, lane);
                mma_tf32(acc[nt], a, b[0], b[1]);
            }
        }
        __syncthreads();
    }
    float* sXf = (float*)sX;
    int r = m0 + (lane >> 2), cb = (lane & 3) * 2;
#pragma unroll
    for (int t = 0; t < 8; t++) {
        int col = n0 + t * 8 + cb;
        sXf[r * 132 + col] = acc[t][0];
        sXf[r * 132 + col + 1] = acc[t][1];
        sXf[(r + 8) * 132 + col] = acc[t][2];
        sXf[(r + 8) * 132 + col + 1] = acc[t][3];
    }
    __syncthreads();
#pragma unroll
    for (int i = 0; i < 8; i++) {
        int rr = warp * 8 + i;
        float4 v = *(const float4*)&sXf[rr * 132 + lane * 4];
        float s = v.x + v.y + v.z + v.w;
        float q = v.x * v.x + v.y * v.y + v.z * v.z + v.w * v.w;
        s = warp_sum(s); q = warp_sum(q);
        float m = s * (1.f / DM);
        float rs = rsqrtf(q * (1.f / DM) - m * m + LNE);
        uint4 o;
        o.x = f2tf((v.x - m) * rs); o.y = f2tf((v.y - m) * rs);
        o.z = f2tf((v.z - m) * rs); o.w = f2tf((v.w - m) * rs);
        __syncwarp();
        *(uint4*)&sX[rr * 132 + lane * 4] = o;
    }
    __syncthreads();
    uint32_t* sBw = smv + 8448;
#pragma unroll 1
    for (int w = 0; w < 4; w++) {
        const uint32_t* Bt = (w == 0) ? g_Wkt[0] : (w == 1) ? g_Wvt[0]
                           : (w == 2) ? g_Wkt[1] : g_Wvt[1];
        float* C = (w == 0) ? g_K[0] : (w == 1) ? g_V[0]
                 : (w == 2) ? g_K[1] : g_V[1];
#pragma unroll
        for (int u = 0; u < 16; u++) {
            int e = u * 256 + tid;
            int n = e >> 5, kk = (e & 31) * 4;
            *(uint4*)&sBw[n * 132 + kk] = *(const uint4*)&Bt[n * DM + kk];
        }
        __syncthreads();
        float ac[8][4];
#pragma unroll
        for (int t = 0; t < 8; t++)
#pragma unroll
            for (int j = 0; j < 4; j++) ac[t][j] = 0.f;
#pragma unroll
        for (int ks = 0; ks < 16; ks++) {
            int k0 = ks * 8;
            uint32_t a[4];
            ldA(a, sX, m0, k0, 132, lane);
#pragma unroll
            for (int nt = 0; nt < 8; nt++) {
                uint32_t b[2];
                ldB(b, sBw, n0 + nt * 8, k0, 132, lane);
                mma_tf32(ac[nt], a, b[0], b[1]);
            }
        }
#pragma unroll
        for (int t = 0; t < 8; t++) {
            int col = n0 + t * 8 + cb;
            *(float2*)&C[(row0 + r) * DM + col] = make_float2(ac[t][0], ac[t][1]);
            *(float2*)&C[(row0 + r + 8) * DM + col] = make_float2(ac[t][2], ac[t][3]);
        }
        __syncthreads();
    }
}

// ---------------- FFN: fragment-order, X-in-regs, 8 warps ------------------
// smem u32: sW1[2][4096] @0 | sW2[2][4096] @8192 | sH[8][512] @16384 |
//           stage/Wq region @20480 [16384]  -> total 36864 u32 = 147456 B
#define FFN_SMEM (36864 * 4)
#define NCH 64

__global__ void __launch_bounds__(256) ffn_tf32(int l) {
    extern __shared__ uint32_t smf[];
    const uint32_t* W1 = g_W1t[l];
    const uint32_t* W2 = g_W2t[l];
    int tid = threadIdx.x, lane = tid & 31, warp = tid >> 5;
    int m0 = warp * 16;
    size_t row0 = (size_t)blockIdx.x * 128;
    uint32_t sb = cvta_s(smf);
    uint32_t* stg = smf + 20480 + warp * 2048;   // warp-private frag staging
    uint32_t* sH = smf + 16384 + warp * 512;     // warp-private H frags

    // prologue: LN rows m0..m0+15, scatter tf32 into frag-order staging
#pragma unroll
    for (int i = 0; i < 16; i++) {
        int r = m0 + i;
        float4 v = *(const float4*)&g_t[(row0 + r) * DM + lane * 4];
        float s = v.x + v.y + v.z + v.w;
        float q = v.x * v.x + v.y * v.y + v.z * v.z + v.w * v.w;
        s = warp_sum(s); q = warp_sum(q);
        float m = s * (1.f / DM);
        float rs = rsqrtf(q * (1.f / DM) - m * m + LNE);
        float x[4] = {(v.x - m) * rs, (v.y - m) * rs, (v.z - m) * rs, (v.w - m) * rs};
        int ks = lane >> 1;
        int wbase = ((lane & 1) << 1) + (i >> 3);   // wd
        int flb = (i & 7) * 4;
#pragma unroll
        for (int j = 0; j < 4; j++)
            stg[ks * 128 + (flb + j) * 4 + wbase] = f2tf(x[j]);
    }
    __syncwarp();
    uint32_t Xf[16][4];
#pragma unroll
    for (int ks = 0; ks < 16; ks++)
        *(uint4*)Xf[ks] = *(const uint4*)&stg[ks * 128 + lane * 4];

    // preload chunk 0 into buf 0
    {
        uint32_t w1d = sb, w2d = sb + 8192 * 4;
#pragma unroll
        for (int u = 0; u < 4; u++) {
            int e = u * 256 + tid;
            CP16(w1d + e * 16, W1 + e * 4);
            CP16(w2d + e * 16, W2 + e * 4);
        }
        CP_COMMIT();
    }

    float acc2[16][4];
#pragma unroll
    for (int t = 0; t < 16; t++)
#pragma unroll
        for (int j = 0; j < 4; j++) acc2[t][j] = 0.f;

    for (int i = 0; i < NCH; i++) {
        int buf = i & 1, nb = buf ^ 1;
        __syncthreads();  // prior reads of buffer nb done
        if (i + 1 < NCH) {
            uint32_t w1d = sb + nb * 4096 * 4;
            uint32_t w2d = sb + (8192 + nb * 4096) * 4;
            const uint32_t* W1s = W1 + (size_t)(i + 1) * 4096;
            const uint32_t* W2s = W2 + (size_t)(i + 1) * 4096;
#pragma unroll
            for (int u = 0; u < 4; u++) {
                int e = u * 256 + tid;
                CP16(w1d + e * 16, W1s + e * 4);
                CP16(w2d + e * 16, W2s + e * 4);
            }
        }
        CP_COMMIT();
        CP_WAIT1();
        __syncthreads();
        const uint32_t* w1 = smf + buf * 4096;
        const uint32_t* w2 = smf + 8192 + buf * 4096;

        // stage1: acc1[4] = X(m16) @ W1chunk(n32), frag LDS.128
        float acc1[4][4];
#pragma unroll
        for (int t = 0; t < 4; t++)
#pragma unroll
            for (int j = 0; j < 4; j++) acc1[t][j] = 0.f;
#pragma unroll
        for (int p = 0; p < 8; p++) {
#pragma unroll
            for (int t = 0; t < 4; t++) {
                uint4 bb = *(const uint4*)&w1[(t * 8 + p) * 128 + lane * 4];
                mma_tf32(acc1[t], Xf[2 * p], bb.x, bb.y);
                mma_tf32(acc1[t], Xf[2 * p + 1], bb.z, bb.w);
            }
        }
        // relu + frag-order scatter into warp-private sH
#pragma unroll
        for (int t = 0; t < 4; t++) {
            float v0 = fmaxf(acc1[t][0], 0.f), v1 = fmaxf(acc1[t][1], 0.f);
            float v2 = fmaxf(acc1[t][2], 0.f), v3 = fmaxf(acc1[t][3], 0.f);
            int cc = 2 * (lane & 3);
            int fl0 = (lane >> 2) * 4 + (cc & 3);
            int hi0 = (cc >> 2) & 1;
            sH[t * 128 + fl0 * 4 + hi0 * 2] = f2tf(v0);
            sH[t * 128 + fl0 * 4 + hi0 * 2 + 1] = f2tf(v2);
            int cc1 = cc + 1;
            int fl1 = (lane >> 2) * 4 + (cc1 & 3);
            int hi1 = (cc1 >> 2) & 1;
            sH[t * 128 + fl1 * 4 + hi1 * 2] = f2tf(v1);
            sH[t * 128 + fl1 * 4 + hi1 * 2 + 1] = f2tf(v3);
        }
        __syncwarp();
        uint32_t Hf[4][4];
#pragma unroll
        for (int ks = 0; ks < 4; ks++)
            *(uint4*)Hf[ks] = *(const uint4*)&sH[ks * 128 + lane * 4];
        // stage2: acc2 += H(m16 x k32) @ W2chunk(n128)
#pragma unroll
        for (int p = 0; p < 2; p++) {
#pragma unroll
            for (int t = 0; t < 16; t++) {
                uint4 bb = *(const uint4*)&w2[(t * 2 + p) * 128 + lane * 4];
                mma_tf32(acc2[t], Hf[2 * p], bb.x, bb.y);
                mma_tf32(acc2[t], Hf[2 * p + 1], bb.z, bb.w);
            }
        }
    }
    __syncthreads();

    // epilogue: residual + quad LN (+ l==0 second LN rescale), write g_t,
    // stage out frags, then fused Q projection.
    int lr = lane >> 2, lc = 2 * (lane & 3);
    size_t r0 = row0 + m0 + lr, r1 = r0 + 8;
    float s0 = 0.f, q0 = 0.f, s1 = 0.f, q1 = 0.f;
#pragma unroll
    for (int t = 0; t < 16; t++) {
        int col = t * 8 + lc;
        float2 x0 = *(const float2*)&g_t[r0 * DM + col];
        float2 x1 = *(const float2*)&g_t[r1 * DM + col];
        acc2[t][0] += x0.x; acc2[t][1] += x0.y;
        acc2[t][2] += x1.x; acc2[t][3] += x1.y;
        s0 += acc2[t][0] + acc2[t][1];
        q0 += acc2[t][0] * acc2[t][0] + acc2[t][1] * acc2[t][1];
        s1 += acc2[t][2] + acc2[t][3];
        q1 += acc2[t][2] * acc2[t][2] + acc2[t][3] * acc2[t][3];
    }
#pragma unroll
    for (int o = 1; o <= 2; o <<= 1) {
        s0 += __shfl_xor_sync(0xffffffffu, s0, o);
        q0 += __shfl_xor_sync(0xffffffffu, q0, o);
        s1 += __shfl_xor_sync(0xffffffffu, s1, o);
        q1 += __shfl_xor_sync(0xffffffffu, q1, o);
    }
    float mu0 = s0 * (1.f / DM), var0 = q0 * (1.f / DM) - mu0 * mu0;
    float mu1 = s1 * (1.f / DM), var1 = q1 * (1.f / DM) - mu1 * mu1;
    float f0 = rsqrtf(var0 + LNE), f1 = rsqrtf(var1 + LNE);
    if (l == 0) {
        f0 *= rsqrtf(var0 / (var0 + LNE) + LNE);
        f1 *= rsqrtf(var1 / (var1 + LNE) + LNE);
    }
    // cooperative load of Wq frag tile into smf[0..16383]
    {
        const uint32_t* Wqg = (l == 0) ? g_Wq1f : g_Wqff;
#pragma unroll
        for (int u = 0; u < 16; u++) {
            int e = u * 256 + tid;
            *(uint4*)&smf[e * 4] = *(const uint4*)&Wqg[e * 4];
        }
    }
#pragma unroll
    for (int t = 0; t < 16; t++) {
        int col = t * 8 + lc;
        float o00 = (acc2[t][0] - mu0) * f0, o01 = (acc2[t][1] - mu0) * f0;
        float o10 = (acc2[t][2] - mu1) * f1, o11 = (acc2[t][3] - mu1) * f1;
        *(float2*)&g_t[r0 * DM + col] = make_float2(o00, o01);
        *(float2*)&g_t[r1 * DM + col] = make_float2(o10, o11);
        // frag staging (ks = t)
        int cc = lc;
        int fla = lr * 4 + (cc & 3), hia = (cc >> 2) & 1;
        stg[t * 128 + fla * 4 + hia * 2] = f2tf(o00);
        stg[t * 128 + fla * 4 + hia * 2 + 1] = f2tf(o10);
        int cc1 = lc + 1;
        int flb2 = lr * 4 + (cc1 & 3), hib = (cc1 >> 2) & 1;
        stg[t * 128 + flb2 * 4 + hib * 2] = f2tf(o01);
        stg[t * 128 + flb2 * 4 + hib * 2 + 1] = f2tf(o11);
    }
    __syncwarp();
    uint32_t Yf[16][4];
#pragma unroll
    for (int ks = 0; ks < 16; ks++)
        *(uint4*)Yf[ks] = *(const uint4*)&stg[ks * 128 + lane * 4];
    __syncthreads();  // Wq tile visible
    float aq[16][4];
#pragma unroll
    for (int t = 0; t < 16; t++)
#pragma unroll
        for (int j = 0; j < 4; j++) aq[t][j] = 0.f;
#pragma unroll
    for (int p = 0; p < 8; p++) {
#pragma unroll
        for (int t = 0; t < 16; t++) {
            uint4 bb = *(const uint4*)&smf[(t * 8 + p) * 128 + lane * 4];
            mma_tf32(aq[t], Yf[2 * p], bb.x, bb.y);
            mma_tf32(aq[t], Yf[2 * p + 1], bb.z, bb.w);
        }
    }
#pragma unroll
    for (int t = 0; t < 16; t++) {
        int col = t * 8 + lc;
        *(float2*)&g_Qp[r0 * DM + col] = make_float2(aq[t][0], aq[t][1]);
        *(float2*)&g_Qp[r1 * DM + col] = make_float2(aq[t][2], aq[t][3]);
    }
}

// ---------------- sliding-window cross attention: 2 frames / block ---------
#define ATTN_SMEM ((4096 + 4096 + 2 * 65 * 128) * 4)

__global__ void __launch_bounds__(256, 2) attn_kernel(int l) {
    extern __shared__ float sm[];
    float* sK = sm + 8192;
    float* sV = sK + 65 * 128;
    const float* Kl = g_K[l];
    const float* Vl = g_V[l];
    int tid = threadIdx.x;
    int grp = tid >> 7, gt = tid & 127;
    int f0 = blockIdx.x * 2;
    int f = f0 + grp;
    size_t base = (size_t)f * NG * DM;
    float* mQ = sm + grp * 2048;
    float* mR = sm + 4096 + grp * 2048;
    int gw = gt >> 5, lane = gt & 31;

    if (l == 0) {
#pragma unroll
        for (int i = 0; i < 16; i++) {
            int e = i * 128 + gt;
            mQ[e] = g_Q0[e];
            mR[e] = g_t0ln[e];
        }
    } else {
#pragma unroll
        for (int i = 0; i < 16; i++) {
            int e = i * 128 + gt;
            mQ[e] = g_Qp[base + e];
            mR[e] = g_t[base + e];
        }
    }
    for (int idx = tid; idx < 65 * 128; idx += 256) {
        int w = idx >> 7;
        int src = f0 - (LQ - 1) + w;
        float kv = 0.f, vv = 0.f;
        if (src >= 0) {
            kv = Kl[(size_t)src * DM + (idx & 127)];
            vv = Vl[(size_t)src * DM + (idx & 127)];
        }
        sK[idx] = kv;
        sV[idx] = vv;
    }
    __syncthreads();
    int h = gt >> 4, q = gt & 15;
    float4 qv[4];
#pragma unroll
    for (int d = 0; d < 4; d++) qv[d] = *(const float4*)&mQ[q * DM + h * 16 + d * 4];
    float sc[LQ];
    float mx = -1e30f;
#pragma unroll
    for (int k = 0; k < LQ; k++) {
        const float4* kr = (const float4*)&sK[(k + grp) * DM + h * 16];
        float s = 0.f;
#pragma unroll
        for (int d = 0; d < 4; d++) {
            float4 kk = kr[d];
            s += qv[d].x * kk.x + qv[d].y * kk.y + qv[d].z * kk.z + qv[d].w * kk.w;
        }
        s *= 0.25f;
        sc[k] = s;
        mx = fmaxf(mx, s);
    }
    float sum = 0.f;
#pragma unroll
    for (int k = 0; k < LQ; k++) {
        float e = __expf(sc[k] - mx);
        sc[k] = e;
        sum += e;
    }
    float inv = 1.f / sum;
    float4 ctx[4];
#pragma unroll
    for (int d = 0; d < 4; d++) ctx[d] = make_float4(0.f, 0.f, 0.f, 0.f);
#pragma unroll
    for (int k = 0; k < LQ; k++) {
        float p = sc[k];
        const float4* vr = (const float4*)&sV[(k + grp) * DM + h * 16];
#pragma unroll
        for (int d = 0; d < 4; d++) {
            float4 vv = vr[d];
            ctx[d].x += p * vv.x; ctx[d].y += p * vv.y;
            ctx[d].z += p * vv.z; ctx[d].w += p * vv.w;
        }
    }
    __syncthreads();
#pragma unroll
    for (int d = 0; d < 4; d++) {
        float4 o = {ctx[d].x * inv, ctx[d].y * inv, ctx[d].z * inv, ctx[d].w * inv};
        *(float4*)&mQ[q * DM + h * 16 + d * 4] = o;
    }
    __syncthreads();
#pragma unroll
    for (int i = 0; i < 4; i++) {
        int r = gw * 4 + i;
        float vals[4];
        float s = 0.f, qq = 0.f;
#pragma unroll
        for (int j = 0; j < 4; j++) {
            int cc = lane + 32 * j;
            float v = mQ[r * DM + cc] + mR[r * DM + cc];
            vals[j] = v;
            s += v;
            qq += v * v;
        }
        s = warp_sum(s); qq = warp_sum(qq);
        float m = s * (1.f / DM);
        float rs = rsqrtf(qq * (1.f / DM) - m * m + LNE);
#pragma unroll
        for (int j = 0; j < 4; j++)
            g_t[base + r * DM + lane + 32 * j] = (vals[j] - m) * rs;
    }
}

// ---------------- final single-head attention ------------------------------
__global__ void final_kernel(float* __restrict__ out) {
    __shared__ float st[NG * DM];
    __shared__ float sQ[NG * DM];
    __shared__ float sKf[NG * 132];
    __shared__ float sVf[NG * DM];
    __shared__ float sS[NG][NG + 1];
    int tid = threadIdx.x;
    int f = blockIdx.x;
    size_t base = (size_t)f * NG * DM;
#pragma unroll
    for (int i = 0; i < 8; i++) {
        int e = i * 256 + tid, r = e >> 7, c = e & 127;
        st[e] = g_t[base + e];
        sQ[e] = g_Qp[base + e];
        sKf[r * 132 + c] = g_Kf[e];
        sVf[e] = g_Vf[e];
    }
    __syncthreads();
    {
        int qr = tid >> 4, kr = tid & 15;
        float a = 0.f;
        for (int k = 0; k < DM; k++) a += sQ[qr * DM + k] * sKf[kr * 132 + k];
        sS[qr][kr] = a * 0.08838834764831843f;
    }
    __syncthreads();
    if (tid < NG) {
        float mx = -1e30f;
#pragma unroll
        for (int k = 0; k < NG; k++) mx = fmaxf(mx, sS[tid][k]);
        float sum = 0.f;
#pragma unroll
        for (int k = 0; k < NG; k++) {
            float e = __expf(sS[tid][k] - mx);
            sS[tid][k] = e;
            sum += e;
        }
        float inv = 1.f / sum;
#pragma unroll
        for (int k = 0; k < NG; k++) sS[tid][k] *= inv;
    }
    __syncthreads();
#pragma unroll
    for (int i = 0; i < 8; i++) {
        int e = i * 256 + tid, r = e >> 7, c = e & 127;
        float a = 0.f;
#pragma unroll
        for (int k = 0; k < NG; k++) a += sS[r][k] * sVf[k * DM + c];
        sQ[e] = a + st[e];
    }
    __syncthreads();
    int warp = tid >> 5, lane = tid & 31;
#pragma unroll
    for (int i = 0; i < 2; i++) {
        int r = warp * 2 + i;
        float4 v0 = *(const float4*)&sQ[r * DM + lane * 4];
        float s = v0.x + v0.y + v0.z + v0.w;
        float q = v0.x * v0.x + v0.y * v0.y + v0.z * v0.z + v0.w * v0.w;
        s = warp_sum(s); q = warp_sum(q);
        float m = s * (1.f / DM);
        float rs = rsqrtf(q * (1.f / DM) - m * m + LNE);
        float4 o = {(v0.x - m) * rs, (v0.y - m) * rs, (v0.z - m) * rs, (v0.w - m) * rs};
        *(float4*)&out[base + r * DM + lane * 4] = o;
    }
}

extern "C" void kernel_launch(void* const* d_in, const int* in_sizes, int n_in,
                              void* d_out, int out_size) {
    const float* g    = (const float*)d_in[0];
    const float* LF   = (const float*)d_in[1];
    const float* Wvis = (const float*)d_in[2];
    const float* Wtxt = (const float*)d_in[3];
    const float* Wq   = (const float*)d_in[4];
    const float* Wk   = (const float*)d_in[5];
    const float* Wv   = (const float*)d_in[6];
    const float* W1   = (const float*)d_in[7];
    const float* W2   = (const float*)d_in[8];
    const float* Wqf  = (const float*)d_in[9];
    const float* Wkf  = (const float*)d_in[10];
    const float* Wvf  = (const float*)d_in[11];
    float* out = (float*)d_out;

    cudaFuncSetAttribute(attn_kernel, cudaFuncAttributeMaxDynamicSharedMemorySize, ATTN_SMEM);
    cudaFuncSetAttribute(viskv_kernel, cudaFuncAttributeMaxDynamicSharedMemorySize, VISKV_SMEM);
    cudaFuncSetAttribute(ffn_tf32, cudaFuncAttributeMaxDynamicSharedMemorySize, FFN_SMEM);

    convtext_kernel<<<dim3(1024, 12), 256>>>(W1, W2, Wq, Wk, Wv, Wqf, Wvis,
                                             g, Wtxt, Wkf, Wvf);              // 0
    viskv_kernel<<<TFR / 64, 256, VISKV_SMEM>>>(LF);                          // 1
    attn_kernel<<<TFR / 2, 256, ATTN_SMEM>>>(0);                              // 2
    ffn_tf32<<<NTOK / 128, 256, FFN_SMEM>>>(0);                               // 3 <- profile slot
    attn_kernel<<<TFR / 2, 256, ATTN_SMEM>>>(1);                              // 4
    ffn_tf32<<<NTOK / 128, 256, FFN_SMEM>>>(1);                               // 5
    final_kernel<<<TFR, 256>>>(out);                                          // 6
}